// round 2
// baseline (speedup 1.0000x reference)
#include <cuda_runtime.h>
#include <float.h>

#define NTOK 2048
#define DM   1024
#define NH   16
#define HD   64

// Scratch (allocation-free rule: __device__ globals)
__device__ float g_Q[NTOK * DM];
__device__ float g_K[NTOK * DM];
__device__ float g_V[NTOK * DM];
__device__ float g_O[NTOK * DM];

// ---------------------------------------------------------------------------
// GEMM: C[M,Nc] = A[M,K] @ B[K,Nc] + bias,  M=2048, Nc=K=1024
// 128x128 block tile, BK=8, 256 threads, 8x8 per-thread microtile.
// ---------------------------------------------------------------------------
__global__ __launch_bounds__(256)
void gemm_bias_kernel(const float* __restrict__ A, const float* __restrict__ B,
                      const float* __restrict__ bias, float* __restrict__ C)
{
    const int Nc = DM, K = DM;
    __shared__ __align__(16) float As[8][132];   // [k][m], padded
    __shared__ __align__(16) float Bs[8][128];   // [k][n]

    const int tid = threadIdx.x;
    const int tx = tid & 15, ty = tid >> 4;      // 16x16 thread grid
    const int row0 = blockIdx.y * 128, col0 = blockIdx.x * 128;

    // A staging: thread -> (row arow, k-offset ak..ak+3)
    const int arow = tid >> 1;           // 0..127
    const int ak   = (tid & 1) << 2;     // 0 or 4
    // B staging: thread -> (k-row bk, col bn..bn+3)
    const int bk = tid >> 5;             // 0..7
    const int bn = (tid & 31) << 2;      // 0..124

    const float* Aptr = A + (row0 + arow) * K + ak;
    const float* Bptr = B + bk * Nc + col0 + bn;

    float acc[8][8] = {};

    for (int k0 = 0; k0 < K; k0 += 8) {
        float4 av = *reinterpret_cast<const float4*>(Aptr + k0);
        float4 bv = *reinterpret_cast<const float4*>(Bptr + (size_t)k0 * Nc);
        As[ak + 0][arow] = av.x;
        As[ak + 1][arow] = av.y;
        As[ak + 2][arow] = av.z;
        As[ak + 3][arow] = av.w;
        *reinterpret_cast<float4*>(&Bs[bk][bn]) = bv;
        __syncthreads();

        #pragma unroll
        for (int kk = 0; kk < 8; kk++) {
            float a[8], b[8];
            *reinterpret_cast<float4*>(a)     = *reinterpret_cast<const float4*>(&As[kk][ty * 8]);
            *reinterpret_cast<float4*>(a + 4) = *reinterpret_cast<const float4*>(&As[kk][ty * 8 + 4]);
            *reinterpret_cast<float4*>(b)     = *reinterpret_cast<const float4*>(&Bs[kk][tx * 8]);
            *reinterpret_cast<float4*>(b + 4) = *reinterpret_cast<const float4*>(&Bs[kk][tx * 8 + 4]);
            #pragma unroll
            for (int i = 0; i < 8; i++)
                #pragma unroll
                for (int j = 0; j < 8; j++)
                    acc[i][j] = fmaf(a[i], b[j], acc[i][j]);
        }
        __syncthreads();
    }

    // epilogue: bias add + float4 stores
    float4 bb0 = *reinterpret_cast<const float4*>(&bias[col0 + tx * 8]);
    float4 bb1 = *reinterpret_cast<const float4*>(&bias[col0 + tx * 8 + 4]);
    #pragma unroll
    for (int i = 0; i < 8; i++) {
        const int r = row0 + ty * 8 + i;
        float4 o0, o1;
        o0.x = acc[i][0] + bb0.x; o0.y = acc[i][1] + bb0.y;
        o0.z = acc[i][2] + bb0.z; o0.w = acc[i][3] + bb0.w;
        o1.x = acc[i][4] + bb1.x; o1.y = acc[i][5] + bb1.y;
        o1.z = acc[i][6] + bb1.z; o1.w = acc[i][7] + bb1.w;
        *reinterpret_cast<float4*>(&C[(size_t)r * Nc + col0 + tx * 8])     = o0;
        *reinterpret_cast<float4*>(&C[(size_t)r * Nc + col0 + tx * 8 + 4]) = o1;
    }
}

// ---------------------------------------------------------------------------
// Flash attention (causal), fp32. One block per (q-tile=64 rows, head).
// 256 threads; thread (ty,tx) owns S/O microtile rows ty*4+i, cols tx*4+j.
// Row softmax state replicated across the 16 tx lanes of each row group
// (width-16 shuffle reductions).
// ---------------------------------------------------------------------------
__global__ __launch_bounds__(256)
void flash_kernel(const float* __restrict__ Qg, const float* __restrict__ Kg,
                  const float* __restrict__ Vg, float* __restrict__ Og)
{
    extern __shared__ float sm[];
    float* Qs = sm;                  // [64][65]
    float* Ks = sm + 64 * 65;        // [64][65]
    float* Vs = sm + 2 * 64 * 65;    // [64][65]
    float* Ss = sm + 3 * 64 * 65;    // [64][65]  (P tile)

    const int qb = blockIdx.x;       // 0..31
    const int h  = blockIdx.y;       // 0..15
    const int tid = threadIdx.x;
    const int tx = tid & 15, ty = tid >> 4;
    const int row0 = qb * 64;
    const int cb = h * HD;

    // Load Q tile (64x64)
    #pragma unroll
    for (int s = 0; s < 4; s++) {
        int e = tid + 256 * s;
        int r = e >> 4, c4 = (e & 15) << 2;
        float4 v = *reinterpret_cast<const float4*>(&Qg[(size_t)(row0 + r) * DM + cb + c4]);
        float* d = &Qs[r * 65 + c4];
        d[0] = v.x; d[1] = v.y; d[2] = v.z; d[3] = v.w;
    }

    float m_r[4], l_r[4], o_acc[4][4];
    #pragma unroll
    for (int i = 0; i < 4; i++) {
        m_r[i] = -1e30f; l_r[i] = 0.f;
        #pragma unroll
        for (int j = 0; j < 4; j++) o_acc[i][j] = 0.f;
    }

    for (int kb = 0; kb <= qb; kb++) {
        const int kr0 = kb * 64;
        #pragma unroll
        for (int s = 0; s < 4; s++) {
            int e = tid + 256 * s;
            int r = e >> 4, c4 = (e & 15) << 2;
            float4 kv = *reinterpret_cast<const float4*>(&Kg[(size_t)(kr0 + r) * DM + cb + c4]);
            float4 vv = *reinterpret_cast<const float4*>(&Vg[(size_t)(kr0 + r) * DM + cb + c4]);
            float* dk = &Ks[r * 65 + c4];
            dk[0] = kv.x; dk[1] = kv.y; dk[2] = kv.z; dk[3] = kv.w;
            float* dv = &Vs[r * 65 + c4];
            dv[0] = vv.x; dv[1] = vv.y; dv[2] = vv.z; dv[3] = vv.w;
        }
        __syncthreads();   // also covers the one-time Q load on kb==0

        // S = Q K^T (4x4 per thread)
        float st[4][4] = {};
        #pragma unroll 8
        for (int k = 0; k < 64; k++) {
            float a[4], b[4];
            #pragma unroll
            for (int i = 0; i < 4; i++) a[i] = Qs[(ty * 4 + i) * 65 + k];
            #pragma unroll
            for (int j = 0; j < 4; j++) b[j] = Ks[(tx * 4 + j) * 65 + k];
            #pragma unroll
            for (int i = 0; i < 4; i++)
                #pragma unroll
                for (int j = 0; j < 4; j++)
                    st[i][j] = fmaf(a[i], b[j], st[i][j]);
        }

        // scale + causal mask (only diagonal block is partial)
        const bool diag = (kb == qb);
        #pragma unroll
        for (int i = 0; i < 4; i++)
            #pragma unroll
            for (int j = 0; j < 4; j++) {
                float v = st[i][j] * 0.125f;   // 1/sqrt(64)
                if (diag && (tx * 4 + j) > (ty * 4 + i)) v = -1e30f;
                st[i][j] = v;
            }

        // online softmax: row max / correction / exp / row sum
        float mnew[4], corr[4];
        #pragma unroll
        for (int i = 0; i < 4; i++) {
            float mx = fmaxf(fmaxf(st[i][0], st[i][1]), fmaxf(st[i][2], st[i][3]));
            #pragma unroll
            for (int off = 8; off >= 1; off >>= 1)
                mx = fmaxf(mx, __shfl_xor_sync(0xffffffffu, mx, off, 16));
            mnew[i] = fmaxf(m_r[i], mx);
            corr[i] = __expf(m_r[i] - mnew[i]);
            m_r[i]  = mnew[i];
        }
        #pragma unroll
        for (int i = 0; i < 4; i++) {
            float rs = 0.f;
            #pragma unroll
            for (int j = 0; j < 4; j++) {
                st[i][j] = __expf(st[i][j] - mnew[i]);
                rs += st[i][j];
            }
            #pragma unroll
            for (int off = 8; off >= 1; off >>= 1)
                rs += __shfl_xor_sync(0xffffffffu, rs, off, 16);
            l_r[i] = l_r[i] * corr[i] + rs;
        }

        // stage P, rescale O accumulator
        #pragma unroll
        for (int i = 0; i < 4; i++)
            #pragma unroll
            for (int j = 0; j < 4; j++)
                Ss[(ty * 4 + i) * 65 + tx * 4 + j] = st[i][j];
        #pragma unroll
        for (int i = 0; i < 4; i++)
            #pragma unroll
            for (int j = 0; j < 4; j++)
                o_acc[i][j] *= corr[i];
        __syncthreads();

        // O += P @ V
        #pragma unroll 8
        for (int k = 0; k < 64; k++) {
            float p[4], vv[4];
            #pragma unroll
            for (int i = 0; i < 4; i++) p[i] = Ss[(ty * 4 + i) * 65 + k];
            #pragma unroll
            for (int j = 0; j < 4; j++) vv[j] = Vs[k * 65 + tx * 4 + j];
            #pragma unroll
            for (int i = 0; i < 4; i++)
                #pragma unroll
                for (int j = 0; j < 4; j++)
                    o_acc[i][j] = fmaf(p[i], vv[j], o_acc[i][j]);
        }
        __syncthreads();   // before next iteration overwrites Ks/Vs/Ss
    }

    #pragma unroll
    for (int i = 0; i < 4; i++) {
        const float inv = 1.f / l_r[i];
        const int r = row0 + ty * 4 + i;
        #pragma unroll
        for (int j = 0; j < 4; j++)
            Og[(size_t)r * DM + cb + tx * 4 + j] = o_acc[i][j] * inv;
    }
}

// ---------------------------------------------------------------------------
// Launch
// ---------------------------------------------------------------------------
extern "C" void kernel_launch(void* const* d_in, const int* in_sizes, int n_in,
                              void* d_out, int out_size)
{
    const float* x  = (const float*)d_in[0];
    const float* Wq = (const float*)d_in[1];
    const float* bq = (const float*)d_in[2];
    const float* Wk = (const float*)d_in[3];
    const float* bk = (const float*)d_in[4];
    const float* Wv = (const float*)d_in[5];
    const float* bv = (const float*)d_in[6];
    const float* Wo = (const float*)d_in[7];
    const float* bo = (const float*)d_in[8];
    float* out = (float*)d_out;

    float *Q, *K, *V, *O;
    cudaGetSymbolAddress((void**)&Q, g_Q);
    cudaGetSymbolAddress((void**)&K, g_K);
    cudaGetSymbolAddress((void**)&V, g_V);
    cudaGetSymbolAddress((void**)&O, g_O);

    const int flash_smem = 4 * 64 * 65 * (int)sizeof(float);  // 66560 B
    cudaFuncSetAttribute(flash_kernel, cudaFuncAttributeMaxDynamicSharedMemorySize,
                         flash_smem);

    dim3 gg(DM / 128, NTOK / 128);   // (8, 16)
    gemm_bias_kernel<<<gg, 256>>>(x, Wq, bq, Q);
    gemm_bias_kernel<<<gg, 256>>>(x, Wk, bk, K);
    gemm_bias_kernel<<<gg, 256>>>(x, Wv, bv, V);

    flash_kernel<<<dim3(NTOK / 64, NH), 256, flash_smem>>>(Q, K, V, O);

    gemm_bias_kernel<<<gg, 256>>>(O, Wo, bo, out);
}

// round 4
// speedup vs baseline: 1.5619x; 1.5619x over previous
#include <cuda_runtime.h>
#include <cuda_bf16.h>
#include <cstdint>
#include <float.h>

#define NTOK 2048
#define DM   1024
#define NH   16
#define HD   64

// ---------------------------------------------------------------------------
// Scratch (__device__ globals; allocation-free rule)
// ---------------------------------------------------------------------------
__device__ float g_Q[NTOK * DM];
__device__ float g_K[NTOK * DM];
__device__ float g_V[NTOK * DM];
__device__ float g_O[NTOK * DM];

__device__ __nv_bfloat16 g_xhi[NTOK * DM];
__device__ __nv_bfloat16 g_xlo[NTOK * DM];
__device__ __nv_bfloat16 g_Ohi[NTOK * DM];
__device__ __nv_bfloat16 g_Olo[NTOK * DM];
// transposed weights [N=1024][K=1024], hi/lo
__device__ __nv_bfloat16 g_Wqh[DM * DM], g_Wql[DM * DM];
__device__ __nv_bfloat16 g_Wkh[DM * DM], g_Wkl[DM * DM];
__device__ __nv_bfloat16 g_Wvh[DM * DM], g_Wvl[DM * DM];
__device__ __nv_bfloat16 g_Woh[DM * DM], g_Wol[DM * DM];

// ---------------------------------------------------------------------------
// PTX helpers: ldmatrix + mma.sync (base-target tensor path; tcgen05 is
// unavailable because the harness compiles PTX at compute_103, not 103a)
// ---------------------------------------------------------------------------
__device__ __forceinline__ uint32_t smem_u32(const void* p) {
    uint32_t a;
    asm("{ .reg .u64 t; cvta.to.shared.u64 t, %1; cvt.u32.u64 %0, t; }" : "=r"(a) : "l"(p));
    return a;
}

#define LDMATRIX_X4(r0, r1, r2, r3, addr) \
    asm volatile("ldmatrix.sync.aligned.m8n8.x4.shared.b16 {%0,%1,%2,%3}, [%4];" \
                 : "=r"(r0), "=r"(r1), "=r"(r2), "=r"(r3) : "r"(addr))
#define LDMATRIX_X2(r0, r1, addr) \
    asm volatile("ldmatrix.sync.aligned.m8n8.x2.shared.b16 {%0,%1}, [%2];" \
                 : "=r"(r0), "=r"(r1) : "r"(addr))
#define MMA_BF16(d, a, b) \
    asm volatile("mma.sync.aligned.m16n8k16.row.col.f32.bf16.bf16.f32 " \
                 "{%0,%1,%2,%3}, {%4,%5,%6,%7}, {%8,%9}, {%0,%1,%2,%3};" \
                 : "+f"((d)[0]), "+f"((d)[1]), "+f"((d)[2]), "+f"((d)[3]) \
                 : "r"((a)[0]), "r"((a)[1]), "r"((a)[2]), "r"((a)[3]), \
                   "r"((b)[0]), "r"((b)[1]))

// ---------------------------------------------------------------------------
// fp32 -> (hi, lo) bf16 split, elementwise
// ---------------------------------------------------------------------------
__global__ __launch_bounds__(256)
void convert_split(const float* __restrict__ src, __nv_bfloat16* __restrict__ hi,
                   __nv_bfloat16* __restrict__ lo)
{
    int i4 = blockIdx.x * 256 + threadIdx.x;
    float4 v = reinterpret_cast<const float4*>(src)[i4];
    __nv_bfloat16 h0 = __float2bfloat16(v.x), h1 = __float2bfloat16(v.y);
    __nv_bfloat16 h2 = __float2bfloat16(v.z), h3 = __float2bfloat16(v.w);
    __nv_bfloat16 l0 = __float2bfloat16(v.x - __bfloat162float(h0));
    __nv_bfloat16 l1 = __float2bfloat16(v.y - __bfloat162float(h1));
    __nv_bfloat16 l2 = __float2bfloat16(v.z - __bfloat162float(h2));
    __nv_bfloat16 l3 = __float2bfloat16(v.w - __bfloat162float(h3));
    __nv_bfloat162* hp = reinterpret_cast<__nv_bfloat162*>(hi) + i4 * 2;
    __nv_bfloat162* lp = reinterpret_cast<__nv_bfloat162*>(lo) + i4 * 2;
    hp[0] = __nv_bfloat162(h0, h1); hp[1] = __nv_bfloat162(h2, h3);
    lp[0] = __nv_bfloat162(l0, l1); lp[1] = __nv_bfloat162(l2, l3);
}

// ---------------------------------------------------------------------------
// W [K,N] fp32 -> Wt [N,K] bf16 hi/lo (transpose + split)
// ---------------------------------------------------------------------------
__global__ __launch_bounds__(256)
void transpose_split(const float* __restrict__ W, __nv_bfloat16* __restrict__ Thi,
                     __nv_bfloat16* __restrict__ Tlo)
{
    __shared__ float t[32][33];
    const int n0 = blockIdx.x * 32, k0 = blockIdx.y * 32;
    const int tx = threadIdx.x & 31, ty = threadIdx.x >> 5;   // 32 x 8
    #pragma unroll
    for (int i = 0; i < 4; i++)
        t[ty + 8 * i][tx] = W[(size_t)(k0 + ty + 8 * i) * DM + n0 + tx];
    __syncthreads();
    #pragma unroll
    for (int i = 0; i < 4; i++) {
        float v = t[tx][ty + 8 * i];
        __nv_bfloat16 h = __float2bfloat16(v);
        __nv_bfloat16 l = __float2bfloat16(v - __bfloat162float(h));
        size_t idx = (size_t)(n0 + ty + 8 * i) * DM + k0 + tx;
        Thi[idx] = h; Tlo[idx] = l;
    }
}

// ---------------------------------------------------------------------------
// Tensor-core GEMM via mma.sync: C[M,N] = A @ Wt^T + bias, split precision
//   A = (Ahi, Alo) [M,K] bf16;  B = (Bhi, Blo) [N,K] bf16 (row-major over N)
//   C = Ah*Bh + Al*Bh + Ah*Bl  (fp32 accum)
// 128x128 CTA tile, BK=32, 256 threads = 8 warps (2 M x 4 N), 64x32 warp tile.
// Smem rows padded to 40 bf16 (80 B) -> conflict-free ldmatrix.
// ---------------------------------------------------------------------------
#define GSTRIDE 40
#define GMAT_B  (128 * GSTRIDE * 2)    // 10240 B per matrix
#define G_SMEM  (4 * GMAT_B)           // 40960 B

__global__ __launch_bounds__(256)
void gemm_mma(const __nv_bfloat16* __restrict__ Ahi, const __nv_bfloat16* __restrict__ Alo,
              const __nv_bfloat16* __restrict__ Bhi, const __nv_bfloat16* __restrict__ Blo,
              const float* __restrict__ bias, float* __restrict__ C)
{
    extern __shared__ char sm[];
    const int tid  = threadIdx.x;
    const int wid  = tid >> 5, lane = tid & 31;
    const int wm   = wid >> 2, wn = wid & 3;          // 2 x 4 warp grid
    const int col0 = blockIdx.x * 128;                // N
    const int row0 = blockIdx.y * 128;                // M

    const uint32_t sbase = smem_u32(sm);
    // matrix order in smem: Ahi, Alo, Bhi, Blo
    const uint32_t sAh = sbase, sAl = sbase + GMAT_B;
    const uint32_t sBh = sbase + 2 * GMAT_B, sBl = sbase + 3 * GMAT_B;

    const __nv_bfloat16* srcs[4] = { Ahi, Alo, Bhi, Blo };

    // staging map: vid in [0,512): r = vid>>2 (row 0..127), c8 = (vid&3)*8
    const int st_r  = (tid + 0)   >> 2, st_c0 = ((tid + 0)   & 3) << 3;
    const int st_r1 = (tid + 256) >> 2, st_c1 = ((tid + 256) & 3) << 3;

    uint4 pre[8];
    #pragma unroll
    for (int t = 0; t < 4; t++) {
        const int gr0 = (t < 2) ? row0 : col0;
        const __nv_bfloat16* s = srcs[t];
        pre[t * 2 + 0] = *reinterpret_cast<const uint4*>(s + (size_t)(gr0 + st_r)  * DM + st_c0);
        pre[t * 2 + 1] = *reinterpret_cast<const uint4*>(s + (size_t)(gr0 + st_r1) * DM + st_c1);
    }

    // fragment smem offsets (bytes)
    const int aRow = wm * 64 + (lane & 15);
    const int aK8  = (lane >> 4) << 3;
    const int bl   = lane & 15;
    const int bRow = wn * 32 + (bl & 7);
    const int bK8  = (bl >> 3) << 3;

    float acc[4][4][4] = {};   // [mt][nt][4]

    for (int c = 0; c < DM / 32; c++) {
        // store prefetched chunk into smem
        {
            uint32_t d0 = (uint32_t)(st_r  * GSTRIDE + st_c0) * 2;
            uint32_t d1 = (uint32_t)(st_r1 * GSTRIDE + st_c1) * 2;
            *reinterpret_cast<uint4*>(sm + 0 * GMAT_B + d0) = pre[0];
            *reinterpret_cast<uint4*>(sm + 0 * GMAT_B + d1) = pre[1];
            *reinterpret_cast<uint4*>(sm + 1 * GMAT_B + d0) = pre[2];
            *reinterpret_cast<uint4*>(sm + 1 * GMAT_B + d1) = pre[3];
            *reinterpret_cast<uint4*>(sm + 2 * GMAT_B + d0) = pre[4];
            *reinterpret_cast<uint4*>(sm + 2 * GMAT_B + d1) = pre[5];
            *reinterpret_cast<uint4*>(sm + 3 * GMAT_B + d0) = pre[6];
            *reinterpret_cast<uint4*>(sm + 3 * GMAT_B + d1) = pre[7];
        }
        __syncthreads();

        // prefetch next chunk (overlaps with MMA below)
        if (c + 1 < DM / 32) {
            const int k0n = (c + 1) * 32;
            #pragma unroll
            for (int t = 0; t < 4; t++) {
                const int gr0 = (t < 2) ? row0 : col0;
                const __nv_bfloat16* s = srcs[t];
                pre[t * 2 + 0] = *reinterpret_cast<const uint4*>(s + (size_t)(gr0 + st_r)  * DM + k0n + st_c0);
                pre[t * 2 + 1] = *reinterpret_cast<const uint4*>(s + (size_t)(gr0 + st_r1) * DM + k0n + st_c1);
            }
        }

        // compute this chunk: 2 k-steps of 16
        #pragma unroll
        for (int ks = 0; ks < 32; ks += 16) {
            uint32_t bh[4][2], blo[4][2];
            #pragma unroll
            for (int nt = 0; nt < 4; nt++) {
                uint32_t off = (uint32_t)((bRow + nt * 8) * GSTRIDE + ks + bK8) * 2;
                LDMATRIX_X2(bh[nt][0],  bh[nt][1],  sBh + off);
                LDMATRIX_X2(blo[nt][0], blo[nt][1], sBl + off);
            }
            #pragma unroll
            for (int mt = 0; mt < 4; mt++) {
                uint32_t ah[4], al[4];
                uint32_t off = (uint32_t)((aRow + mt * 16) * GSTRIDE + ks + aK8) * 2;
                LDMATRIX_X4(ah[0], ah[1], ah[2], ah[3], sAh + off);
                LDMATRIX_X4(al[0], al[1], al[2], al[3], sAl + off);
                #pragma unroll
                for (int nt = 0; nt < 4; nt++) MMA_BF16(acc[mt][nt], ah, bh[nt]);
                #pragma unroll
                for (int nt = 0; nt < 4; nt++) MMA_BF16(acc[mt][nt], al, bh[nt]);
                #pragma unroll
                for (int nt = 0; nt < 4; nt++) MMA_BF16(acc[mt][nt], ah, blo[nt]);
            }
        }
        __syncthreads();
    }

    // epilogue: acc -> gmem with bias
    const int qr = lane >> 2, qc = (lane & 3) << 1;
    #pragma unroll
    for (int nt = 0; nt < 4; nt++) {
        const int col = col0 + wn * 32 + nt * 8 + qc;
        const float2 bb = *reinterpret_cast<const float2*>(&bias[col]);
        #pragma unroll
        for (int mt = 0; mt < 4; mt++) {
            const int r = row0 + wm * 64 + mt * 16 + qr;
            float2 o0 = { acc[mt][nt][0] + bb.x, acc[mt][nt][1] + bb.y };
            float2 o1 = { acc[mt][nt][2] + bb.x, acc[mt][nt][3] + bb.y };
            *reinterpret_cast<float2*>(&C[(size_t)r * DM + col])       = o0;
            *reinterpret_cast<float2*>(&C[(size_t)(r + 8) * DM + col]) = o1;
        }
    }
}

// ---------------------------------------------------------------------------
// Flash attention (causal), fp32 — unchanged from passing round 2.
// ---------------------------------------------------------------------------
__global__ __launch_bounds__(256)
void flash_kernel(const float* __restrict__ Qg, const float* __restrict__ Kg,
                  const float* __restrict__ Vg, float* __restrict__ Og)
{
    extern __shared__ float smf[];
    float* Qs = smf;
    float* Ks = smf + 64 * 65;
    float* Vs = smf + 2 * 64 * 65;
    float* Ss = smf + 3 * 64 * 65;

    const int qb = blockIdx.x;
    const int h  = blockIdx.y;
    const int tid = threadIdx.x;
    const int tx = tid & 15, ty = tid >> 4;
    const int row0 = qb * 64;
    const int cb = h * HD;

    #pragma unroll
    for (int s = 0; s < 4; s++) {
        int e = tid + 256 * s;
        int r = e >> 4, c4 = (e & 15) << 2;
        float4 v = *reinterpret_cast<const float4*>(&Qg[(size_t)(row0 + r) * DM + cb + c4]);
        float* d = &Qs[r * 65 + c4];
        d[0] = v.x; d[1] = v.y; d[2] = v.z; d[3] = v.w;
    }

    float m_r[4], l_r[4], o_acc[4][4];
    #pragma unroll
    for (int i = 0; i < 4; i++) {
        m_r[i] = -1e30f; l_r[i] = 0.f;
        #pragma unroll
        for (int j = 0; j < 4; j++) o_acc[i][j] = 0.f;
    }

    for (int kb = 0; kb <= qb; kb++) {
        const int kr0 = kb * 64;
        #pragma unroll
        for (int s = 0; s < 4; s++) {
            int e = tid + 256 * s;
            int r = e >> 4, c4 = (e & 15) << 2;
            float4 kv = *reinterpret_cast<const float4*>(&Kg[(size_t)(kr0 + r) * DM + cb + c4]);
            float4 vv = *reinterpret_cast<const float4*>(&Vg[(size_t)(kr0 + r) * DM + cb + c4]);
            float* dk = &Ks[r * 65 + c4];
            dk[0] = kv.x; dk[1] = kv.y; dk[2] = kv.z; dk[3] = kv.w;
            float* dv = &Vs[r * 65 + c4];
            dv[0] = vv.x; dv[1] = vv.y; dv[2] = vv.z; dv[3] = vv.w;
        }
        __syncthreads();

        float st[4][4] = {};
        #pragma unroll 8
        for (int k = 0; k < 64; k++) {
            float a[4], b[4];
            #pragma unroll
            for (int i = 0; i < 4; i++) a[i] = Qs[(ty * 4 + i) * 65 + k];
            #pragma unroll
            for (int j = 0; j < 4; j++) b[j] = Ks[(tx * 4 + j) * 65 + k];
            #pragma unroll
            for (int i = 0; i < 4; i++)
                #pragma unroll
                for (int j = 0; j < 4; j++)
                    st[i][j] = fmaf(a[i], b[j], st[i][j]);
        }

        const bool diag = (kb == qb);
        #pragma unroll
        for (int i = 0; i < 4; i++)
            #pragma unroll
            for (int j = 0; j < 4; j++) {
                float v = st[i][j] * 0.125f;
                if (diag && (tx * 4 + j) > (ty * 4 + i)) v = -1e30f;
                st[i][j] = v;
            }

        float mnew[4], corr[4];
        #pragma unroll
        for (int i = 0; i < 4; i++) {
            float mx = fmaxf(fmaxf(st[i][0], st[i][1]), fmaxf(st[i][2], st[i][3]));
            #pragma unroll
            for (int off = 8; off >= 1; off >>= 1)
                mx = fmaxf(mx, __shfl_xor_sync(0xffffffffu, mx, off, 16));
            mnew[i] = fmaxf(m_r[i], mx);
            corr[i] = __expf(m_r[i] - mnew[i]);
            m_r[i]  = mnew[i];
        }
        #pragma unroll
        for (int i = 0; i < 4; i++) {
            float rs = 0.f;
            #pragma unroll
            for (int j = 0; j < 4; j++) {
                st[i][j] = __expf(st[i][j] - mnew[i]);
                rs += st[i][j];
            }
            #pragma unroll
            for (int off = 8; off >= 1; off >>= 1)
                rs += __shfl_xor_sync(0xffffffffu, rs, off, 16);
            l_r[i] = l_r[i] * corr[i] + rs;
        }

        #pragma unroll
        for (int i = 0; i < 4; i++)
            #pragma unroll
            for (int j = 0; j < 4; j++)
                Ss[(ty * 4 + i) * 65 + tx * 4 + j] = st[i][j];
        #pragma unroll
        for (int i = 0; i < 4; i++)
            #pragma unroll
            for (int j = 0; j < 4; j++)
                o_acc[i][j] *= corr[i];
        __syncthreads();

        #pragma unroll 8
        for (int k = 0; k < 64; k++) {
            float p[4], vv[4];
            #pragma unroll
            for (int i = 0; i < 4; i++) p[i] = Ss[(ty * 4 + i) * 65 + k];
            #pragma unroll
            for (int j = 0; j < 4; j++) vv[j] = Vs[k * 65 + tx * 4 + j];
            #pragma unroll
            for (int i = 0; i < 4; i++)
                #pragma unroll
                for (int j = 0; j < 4; j++)
                    o_acc[i][j] = fmaf(p[i], vv[j], o_acc[i][j]);
        }
        __syncthreads();
    }

    #pragma unroll
    for (int i = 0; i < 4; i++) {
        const float inv = 1.f / l_r[i];
        const int r = row0 + ty * 4 + i;
        #pragma unroll
        for (int j = 0; j < 4; j++)
            Og[(size_t)r * DM + cb + tx * 4 + j] = o_acc[i][j] * inv;
    }
}

// ---------------------------------------------------------------------------
// Launch
// ---------------------------------------------------------------------------
extern "C" void kernel_launch(void* const* d_in, const int* in_sizes, int n_in,
                              void* d_out, int out_size)
{
    const float* x  = (const float*)d_in[0];
    const float* Wq = (const float*)d_in[1];
    const float* bq = (const float*)d_in[2];
    const float* Wk = (const float*)d_in[3];
    const float* bk = (const float*)d_in[4];
    const float* Wv = (const float*)d_in[5];
    const float* bv = (const float*)d_in[6];
    const float* Wo = (const float*)d_in[7];
    const float* bo = (const float*)d_in[8];
    float* out = (float*)d_out;

    float *Q, *K, *V, *O;
    cudaGetSymbolAddress((void**)&Q, g_Q);
    cudaGetSymbolAddress((void**)&K, g_K);
    cudaGetSymbolAddress((void**)&V, g_V);
    cudaGetSymbolAddress((void**)&O, g_O);
    __nv_bfloat16 *xhi, *xlo, *Ohi, *Olo;
    cudaGetSymbolAddress((void**)&xhi, g_xhi);
    cudaGetSymbolAddress((void**)&xlo, g_xlo);
    cudaGetSymbolAddress((void**)&Ohi, g_Ohi);
    cudaGetSymbolAddress((void**)&Olo, g_Olo);
    __nv_bfloat16 *Wqh, *Wql, *Wkh, *Wkl, *Wvh, *Wvl, *Woh, *Wol;
    cudaGetSymbolAddress((void**)&Wqh, g_Wqh); cudaGetSymbolAddress((void**)&Wql, g_Wql);
    cudaGetSymbolAddress((void**)&Wkh, g_Wkh); cudaGetSymbolAddress((void**)&Wkl, g_Wkl);
    cudaGetSymbolAddress((void**)&Wvh, g_Wvh); cudaGetSymbolAddress((void**)&Wvl, g_Wvl);
    cudaGetSymbolAddress((void**)&Woh, g_Woh); cudaGetSymbolAddress((void**)&Wol, g_Wol);

    const int flash_smem = 4 * 64 * 65 * (int)sizeof(float);
    cudaFuncSetAttribute(flash_kernel, cudaFuncAttributeMaxDynamicSharedMemorySize, flash_smem);

    dim3 tg(DM / 32, DM / 32);
    dim3 gg(DM / 128, NTOK / 128);   // (8, 16)

    convert_split<<<NTOK * DM / 1024, 256>>>(x, xhi, xlo);
    transpose_split<<<tg, 256>>>(Wq, Wqh, Wql);
    transpose_split<<<tg, 256>>>(Wk, Wkh, Wkl);
    transpose_split<<<tg, 256>>>(Wv, Wvh, Wvl);
    transpose_split<<<tg, 256>>>(Wo, Woh, Wol);

    gemm_mma<<<gg, 256, G_SMEM>>>(xhi, xlo, Wqh, Wql, bq, Q);
    gemm_mma<<<gg, 256, G_SMEM>>>(xhi, xlo, Wkh, Wkl, bk, K);
    gemm_mma<<<gg, 256, G_SMEM>>>(xhi, xlo, Wvh, Wvl, bv, V);

    flash_kernel<<<dim3(NTOK / 64, NH), 256, flash_smem>>>(Q, K, V, O);

    convert_split<<<NTOK * DM / 1024, 256>>>(O, Ohi, Olo);
    gemm_mma<<<gg, 256, G_SMEM>>>(Ohi, Olo, Woh, Wol, bo, out);
}

// round 9
// speedup vs baseline: 3.2103x; 2.0554x over previous
#include <cuda_runtime.h>
#include <cuda_bf16.h>
#include <cstdint>
#include <float.h>

#define NTOK 2048
#define DM   1024
#define NH   16
#define HD   64

// ---------------------------------------------------------------------------
// Scratch (__device__ globals; allocation-free rule)
// ---------------------------------------------------------------------------
__device__ float g_O[NTOK * DM];

__device__ __nv_bfloat16 g_Qh[NTOK * DM], g_Ql[NTOK * DM];
__device__ __nv_bfloat16 g_Kh[NTOK * DM], g_Kl[NTOK * DM];
__device__ __nv_bfloat16 g_Vh[NTOK * DM], g_Vl[NTOK * DM];

__device__ __nv_bfloat16 g_xhi[NTOK * DM];
__device__ __nv_bfloat16 g_xlo[NTOK * DM];
__device__ __nv_bfloat16 g_Ohi[NTOK * DM];
__device__ __nv_bfloat16 g_Olo[NTOK * DM];
// transposed weights [N=1024][K=1024], hi/lo
__device__ __nv_bfloat16 g_Wqh[DM * DM], g_Wql[DM * DM];
__device__ __nv_bfloat16 g_Wkh[DM * DM], g_Wkl[DM * DM];
__device__ __nv_bfloat16 g_Wvh[DM * DM], g_Wvl[DM * DM];
__device__ __nv_bfloat16 g_Woh[DM * DM], g_Wol[DM * DM];

// ---------------------------------------------------------------------------
// PTX helpers (base-target tensor path; tcgen05 unavailable at compute_103)
// ---------------------------------------------------------------------------
__device__ __forceinline__ uint32_t smem_u32(const void* p) {
    uint32_t a;
    asm("{ .reg .u64 t; cvta.to.shared.u64 t, %1; cvt.u32.u64 %0, t; }" : "=r"(a) : "l"(p));
    return a;
}

#define LDMATRIX_X4(r0, r1, r2, r3, addr) \
    asm volatile("ldmatrix.sync.aligned.m8n8.x4.shared.b16 {%0,%1,%2,%3}, [%4];" \
                 : "=r"(r0), "=r"(r1), "=r"(r2), "=r"(r3) : "r"(addr))
#define LDMATRIX_X4T(r0, r1, r2, r3, addr) \
    asm volatile("ldmatrix.sync.aligned.m8n8.x4.trans.shared.b16 {%0,%1,%2,%3}, [%4];" \
                 : "=r"(r0), "=r"(r1), "=r"(r2), "=r"(r3) : "r"(addr))
#define LDMATRIX_X2(r0, r1, addr) \
    asm volatile("ldmatrix.sync.aligned.m8n8.x2.shared.b16 {%0,%1}, [%2];" \
                 : "=r"(r0), "=r"(r1) : "r"(addr))
#define MMA_BF16(d, a, b) \
    asm volatile("mma.sync.aligned.m16n8k16.row.col.f32.bf16.bf16.f32 " \
                 "{%0,%1,%2,%3}, {%4,%5,%6,%7}, {%8,%9}, {%0,%1,%2,%3};" \
                 : "+f"((d)[0]), "+f"((d)[1]), "+f"((d)[2]), "+f"((d)[3]) \
                 : "r"((a)[0]), "r"((a)[1]), "r"((a)[2]), "r"((a)[3]), \
                   "r"((b)[0]), "r"((b)[1]))

__device__ __forceinline__ uint32_t pack_bf16x2(float lo, float hi) {
    __nv_bfloat162 t = __floats2bfloat162_rn(lo, hi);   // .x = lo, .y = hi
    return *reinterpret_cast<uint32_t*>(&t);
}

// ---------------------------------------------------------------------------
// fp32 -> (hi, lo) bf16 split, elementwise
// ---------------------------------------------------------------------------
__global__ __launch_bounds__(256)
void convert_split(const float* __restrict__ src, __nv_bfloat16* __restrict__ hi,
                   __nv_bfloat16* __restrict__ lo)
{
    int i4 = blockIdx.x * 256 + threadIdx.x;
    float4 v = reinterpret_cast<const float4*>(src)[i4];
    __nv_bfloat16 h0 = __float2bfloat16(v.x), h1 = __float2bfloat16(v.y);
    __nv_bfloat16 h2 = __float2bfloat16(v.z), h3 = __float2bfloat16(v.w);
    __nv_bfloat16 l0 = __float2bfloat16(v.x - __bfloat162float(h0));
    __nv_bfloat16 l1 = __float2bfloat16(v.y - __bfloat162float(h1));
    __nv_bfloat16 l2 = __float2bfloat16(v.z - __bfloat162float(h2));
    __nv_bfloat16 l3 = __float2bfloat16(v.w - __bfloat162float(h3));
    __nv_bfloat162* hp = reinterpret_cast<__nv_bfloat162*>(hi) + i4 * 2;
    __nv_bfloat162* lp = reinterpret_cast<__nv_bfloat162*>(lo) + i4 * 2;
    hp[0] = __nv_bfloat162(h0, h1); hp[1] = __nv_bfloat162(h2, h3);
    lp[0] = __nv_bfloat162(l0, l1); lp[1] = __nv_bfloat162(l2, l3);
}

// ---------------------------------------------------------------------------
// W [K,N] fp32 -> Wt [N,K] bf16 hi/lo (transpose + split)
// ---------------------------------------------------------------------------
__global__ __launch_bounds__(256)
void transpose_split(const float* __restrict__ W, __nv_bfloat16* __restrict__ Thi,
                     __nv_bfloat16* __restrict__ Tlo)
{
    __shared__ float t[32][33];
    const int n0 = blockIdx.x * 32, k0 = blockIdx.y * 32;
    const int tx = threadIdx.x & 31, ty = threadIdx.x >> 5;   // 32 x 8
    #pragma unroll
    for (int i = 0; i < 4; i++)
        t[ty + 8 * i][tx] = W[(size_t)(k0 + ty + 8 * i) * DM + n0 + tx];
    __syncthreads();
    #pragma unroll
    for (int i = 0; i < 4; i++) {
        float v = t[tx][ty + 8 * i];
        __nv_bfloat16 h = __float2bfloat16(v);
        __nv_bfloat16 l = __float2bfloat16(v - __bfloat162float(h));
        size_t idx = (size_t)(n0 + ty + 8 * i) * DM + k0 + tx;
        Thi[idx] = h; Tlo[idx] = l;
    }
}

// ---------------------------------------------------------------------------
// Tensor-core GEMM via mma.sync, split precision (Ah*Bh + Al*Bh + Ah*Bl).
// 128x128 CTA tile, BK=32, 256 threads = 8 warps (2 M x 4 N).
// BF16OUT: write (hi, lo) bf16 pair outputs (feeding flash); else fp32.
// ---------------------------------------------------------------------------
#define GSTRIDE 40
#define GMAT_B  (128 * GSTRIDE * 2)    // 10240 B per matrix
#define G_SMEM  (4 * GMAT_B)           // 40960 B

template<bool BF16OUT>
__global__ __launch_bounds__(256)
void gemm_mma(const __nv_bfloat16* __restrict__ Ahi, const __nv_bfloat16* __restrict__ Alo,
              const __nv_bfloat16* __restrict__ Bhi, const __nv_bfloat16* __restrict__ Blo,
              const float* __restrict__ bias, float* __restrict__ C,
              __nv_bfloat16* __restrict__ Cbh, __nv_bfloat16* __restrict__ Cbl)
{
    extern __shared__ char sm[];
    const int tid  = threadIdx.x;
    const int wid  = tid >> 5, lane = tid & 31;
    const int wm   = wid >> 2, wn = wid & 3;          // 2 x 4 warp grid
    const int col0 = blockIdx.x * 128;                // N
    const int row0 = blockIdx.y * 128;                // M

    const uint32_t sbase = smem_u32(sm);
    const uint32_t sAh = sbase, sAl = sbase + GMAT_B;
    const uint32_t sBh = sbase + 2 * GMAT_B, sBl = sbase + 3 * GMAT_B;

    const __nv_bfloat16* srcs[4] = { Ahi, Alo, Bhi, Blo };

    const int st_r  = (tid + 0)   >> 2, st_c0 = ((tid + 0)   & 3) << 3;
    const int st_r1 = (tid + 256) >> 2, st_c1 = ((tid + 256) & 3) << 3;

    uint4 pre[8];
    #pragma unroll
    for (int t = 0; t < 4; t++) {
        const int gr0 = (t < 2) ? row0 : col0;
        const __nv_bfloat16* s = srcs[t];
        pre[t * 2 + 0] = *reinterpret_cast<const uint4*>(s + (size_t)(gr0 + st_r)  * DM + st_c0);
        pre[t * 2 + 1] = *reinterpret_cast<const uint4*>(s + (size_t)(gr0 + st_r1) * DM + st_c1);
    }

    const int aRow = wm * 64 + (lane & 15);
    const int aK8  = (lane >> 4) << 3;
    const int bl   = lane & 15;
    const int bRow = wn * 32 + (bl & 7);
    const int bK8  = (bl >> 3) << 3;

    float acc[4][4][4] = {};

    for (int c = 0; c < DM / 32; c++) {
        {
            uint32_t d0 = (uint32_t)(st_r  * GSTRIDE + st_c0) * 2;
            uint32_t d1 = (uint32_t)(st_r1 * GSTRIDE + st_c1) * 2;
            *reinterpret_cast<uint4*>(sm + 0 * GMAT_B + d0) = pre[0];
            *reinterpret_cast<uint4*>(sm + 0 * GMAT_B + d1) = pre[1];
            *reinterpret_cast<uint4*>(sm + 1 * GMAT_B + d0) = pre[2];
            *reinterpret_cast<uint4*>(sm + 1 * GMAT_B + d1) = pre[3];
            *reinterpret_cast<uint4*>(sm + 2 * GMAT_B + d0) = pre[4];
            *reinterpret_cast<uint4*>(sm + 2 * GMAT_B + d1) = pre[5];
            *reinterpret_cast<uint4*>(sm + 3 * GMAT_B + d0) = pre[6];
            *reinterpret_cast<uint4*>(sm + 3 * GMAT_B + d1) = pre[7];
        }
        __syncthreads();

        if (c + 1 < DM / 32) {
            const int k0n = (c + 1) * 32;
            #pragma unroll
            for (int t = 0; t < 4; t++) {
                const int gr0 = (t < 2) ? row0 : col0;
                const __nv_bfloat16* s = srcs[t];
                pre[t * 2 + 0] = *reinterpret_cast<const uint4*>(s + (size_t)(gr0 + st_r)  * DM + k0n + st_c0);
                pre[t * 2 + 1] = *reinterpret_cast<const uint4*>(s + (size_t)(gr0 + st_r1) * DM + k0n + st_c1);
            }
        }

        #pragma unroll
        for (int ks = 0; ks < 32; ks += 16) {
            uint32_t bh[4][2], blo_[4][2];
            #pragma unroll
            for (int nt = 0; nt < 4; nt++) {
                uint32_t off = (uint32_t)((bRow + nt * 8) * GSTRIDE + ks + bK8) * 2;
                LDMATRIX_X2(bh[nt][0],   bh[nt][1],   sBh + off);
                LDMATRIX_X2(blo_[nt][0], blo_[nt][1], sBl + off);
            }
            #pragma unroll
            for (int mt = 0; mt < 4; mt++) {
                uint32_t ah[4], al[4];
                uint32_t off = (uint32_t)((aRow + mt * 16) * GSTRIDE + ks + aK8) * 2;
                LDMATRIX_X4(ah[0], ah[1], ah[2], ah[3], sAh + off);
                LDMATRIX_X4(al[0], al[1], al[2], al[3], sAl + off);
                #pragma unroll
                for (int nt = 0; nt < 4; nt++) MMA_BF16(acc[mt][nt], ah, bh[nt]);
                #pragma unroll
                for (int nt = 0; nt < 4; nt++) MMA_BF16(acc[mt][nt], al, bh[nt]);
                #pragma unroll
                for (int nt = 0; nt < 4; nt++) MMA_BF16(acc[mt][nt], ah, blo_[nt]);
            }
        }
        __syncthreads();
    }

    const int qr = lane >> 2, qc = (lane & 3) << 1;
    #pragma unroll
    for (int nt = 0; nt < 4; nt++) {
        const int col = col0 + wn * 32 + nt * 8 + qc;
        const float2 bb = *reinterpret_cast<const float2*>(&bias[col]);
        #pragma unroll
        for (int mt = 0; mt < 4; mt++) {
            const int r = row0 + wm * 64 + mt * 16 + qr;
            float v00 = acc[mt][nt][0] + bb.x, v01 = acc[mt][nt][1] + bb.y;
            float v10 = acc[mt][nt][2] + bb.x, v11 = acc[mt][nt][3] + bb.y;
            if (BF16OUT) {
                float h00 = __bfloat162float(__float2bfloat16(v00));
                float h01 = __bfloat162float(__float2bfloat16(v01));
                float h10 = __bfloat162float(__float2bfloat16(v10));
                float h11 = __bfloat162float(__float2bfloat16(v11));
                *reinterpret_cast<uint32_t*>(&Cbh[(size_t)r * DM + col])       = pack_bf16x2(h00, h01);
                *reinterpret_cast<uint32_t*>(&Cbh[(size_t)(r + 8) * DM + col]) = pack_bf16x2(h10, h11);
                *reinterpret_cast<uint32_t*>(&Cbl[(size_t)r * DM + col])       = pack_bf16x2(v00 - h00, v01 - h01);
                *reinterpret_cast<uint32_t*>(&Cbl[(size_t)(r + 8) * DM + col]) = pack_bf16x2(v10 - h10, v11 - h11);
            } else {
                float2 o0 = { v00, v01 }, o1 = { v10, v11 };
                *reinterpret_cast<float2*>(&C[(size_t)r * DM + col])       = o0;
                *reinterpret_cast<float2*>(&C[(size_t)(r + 8) * DM + col]) = o1;
            }
        }
    }
}

// ---------------------------------------------------------------------------
// Tensor-core flash attention (causal), SPLIT-PRECISION bf16 mma.sync.
// S = Qh Kh + Ql Kh + Qh Kl;  O += Ph Vh + Pl Vh + Ph Vl  (fp32 softmax).
// CTA = 128 q-rows x 1 head; 8 warps x 16 rows; K-tile = 64.
// Pairing: CTA handles q-tiles {p, 15-p} -> uniform 36 K-tiles per CTA.
// ---------------------------------------------------------------------------
#define FSTR 72   // smem row stride (bf16 elems)
// dynamic smem layout (element offsets): Qh 128 rows, Ql 128, Kh 64, Kl 64, Vh 64, Vl 64
#define F_QH 0
#define F_QL (128 * FSTR)
#define F_KH (256 * FSTR)
#define F_KL (320 * FSTR)
#define F_VH (384 * FSTR)
#define F_VL (448 * FSTR)
#define F_SMEM_B (512 * FSTR * 2)   // 73728 B

__global__ __launch_bounds__(256, 1)
void flash_mma(const __nv_bfloat16* __restrict__ Qh, const __nv_bfloat16* __restrict__ Ql,
               const __nv_bfloat16* __restrict__ Kh, const __nv_bfloat16* __restrict__ Kl,
               const __nv_bfloat16* __restrict__ Vh, const __nv_bfloat16* __restrict__ Vl,
               float* __restrict__ Og)
{
    extern __shared__ __nv_bfloat16 fsm[];

    const int pairi = blockIdx.x;     // 0..7
    const int h     = blockIdx.y;     // 0..15
    const int tid   = threadIdx.x;
    const int wid   = tid >> 5, lane = tid & 31;
    const int cb    = h * HD;

    const uint32_t sb  = smem_u32(fsm);
    const uint32_t sQh = sb + F_QH * 2, sQl = sb + F_QL * 2;
    const uint32_t sKh = sb + F_KH * 2, sKl = sb + F_KL * 2;
    const uint32_t sVh = sb + F_VH * 2, sVl = sb + F_VL * 2;

    #pragma unroll 1
    for (int half = 0; half < 2; half++) {
        const int qb   = (half == 0) ? pairi : (15 - pairi);
        const int row0 = qb * 128;
        const int kbmax = 2 * qb + 1;   // inclusive

        // stage Q hi/lo tiles (128 x 64 bf16 each)
        #pragma unroll
        for (int s = 0; s < 4; s++) {
            int vid = tid + 256 * s;
            int r = vid >> 3, c8 = (vid & 7) << 3;
            uint4 vh = *reinterpret_cast<const uint4*>(Qh + (size_t)(row0 + r) * DM + cb + c8);
            uint4 vl = *reinterpret_cast<const uint4*>(Ql + (size_t)(row0 + r) * DM + cb + c8);
            *reinterpret_cast<uint4*>(reinterpret_cast<char*>(fsm) + (F_QH + r * FSTR + c8) * 2) = vh;
            *reinterpret_cast<uint4*>(reinterpret_cast<char*>(fsm) + (F_QL + r * FSTR + c8) * 2) = vl;
        }
        __syncthreads();

        // Q fragments (held in regs all half)
        uint32_t qfh[4][4], qfl[4][4];
        {
            uint32_t off = (uint32_t)(((wid * 16 + (lane & 15)) * FSTR + ((lane >> 4) << 3)) * 2);
            #pragma unroll
            for (int kc = 0; kc < 4; kc++) {
                LDMATRIX_X4(qfh[kc][0], qfh[kc][1], qfh[kc][2], qfh[kc][3], sQh + off + kc * 32);
                LDMATRIX_X4(qfl[kc][0], qfl[kc][1], qfl[kc][2], qfl[kc][3], sQl + off + kc * 32);
            }
        }

        float m0 = -1e30f, m1 = -1e30f, l0 = 0.f, l1 = 0.f;
        float o[8][4] = {};

        // K/V staging map: vid 0..511 -> r = vid>>3, c8 = (vid&7)*8; 2 per thread
        const int kv_r0 = (tid + 0)   >> 3, kv_c0 = ((tid + 0)   & 7) << 3;
        const int kv_r1 = (tid + 256) >> 3, kv_c1 = ((tid + 256) & 7) << 3;
        const size_t gkv0 = (size_t)kv_r0 * DM + cb + kv_c0;
        const size_t gkv1 = (size_t)kv_r1 * DM + cb + kv_c1;

        uint4 pkh0 = *reinterpret_cast<const uint4*>(Kh + gkv0);
        uint4 pkh1 = *reinterpret_cast<const uint4*>(Kh + gkv1);
        uint4 pkl0 = *reinterpret_cast<const uint4*>(Kl + gkv0);
        uint4 pkl1 = *reinterpret_cast<const uint4*>(Kl + gkv1);
        uint4 pvh0 = *reinterpret_cast<const uint4*>(Vh + gkv0);
        uint4 pvh1 = *reinterpret_cast<const uint4*>(Vh + gkv1);
        uint4 pvl0 = *reinterpret_cast<const uint4*>(Vl + gkv0);
        uint4 pvl1 = *reinterpret_cast<const uint4*>(Vl + gkv1);

        const int warpR = row0 + wid * 16;   // warp's min q-row

        #pragma unroll 1
        for (int kb = 0; kb <= kbmax; kb++) {
            // store prefetched K/V hi/lo tiles
            {
                char* base = reinterpret_cast<char*>(fsm);
                uint32_t d0 = (uint32_t)(kv_r0 * FSTR + kv_c0) * 2;
                uint32_t d1 = (uint32_t)(kv_r1 * FSTR + kv_c1) * 2;
                *reinterpret_cast<uint4*>(base + F_KH * 2 + d0) = pkh0;
                *reinterpret_cast<uint4*>(base + F_KH * 2 + d1) = pkh1;
                *reinterpret_cast<uint4*>(base + F_KL * 2 + d0) = pkl0;
                *reinterpret_cast<uint4*>(base + F_KL * 2 + d1) = pkl1;
                *reinterpret_cast<uint4*>(base + F_VH * 2 + d0) = pvh0;
                *reinterpret_cast<uint4*>(base + F_VH * 2 + d1) = pvh1;
                *reinterpret_cast<uint4*>(base + F_VL * 2 + d0) = pvl0;
                *reinterpret_cast<uint4*>(base + F_VL * 2 + d1) = pvl1;
            }
            __syncthreads();

            if (kb < kbmax) {
                const size_t nb = (size_t)((kb + 1) * 64) * DM;
                pkh0 = *reinterpret_cast<const uint4*>(Kh + nb + gkv0);
                pkh1 = *reinterpret_cast<const uint4*>(Kh + nb + gkv1);
                pkl0 = *reinterpret_cast<const uint4*>(Kl + nb + gkv0);
                pkl1 = *reinterpret_cast<const uint4*>(Kl + nb + gkv1);
                pvh0 = *reinterpret_cast<const uint4*>(Vh + nb + gkv0);
                pvh1 = *reinterpret_cast<const uint4*>(Vh + nb + gkv1);
                pvl0 = *reinterpret_cast<const uint4*>(Vl + nb + gkv0);
                pvl1 = *reinterpret_cast<const uint4*>(Vl + nb + gkv1);
            }

            // ---- S = Qh Kh + Ql Kh + Qh Kl  (per warp: 16 x 64) ----
            float s[8][4];
            #pragma unroll
            for (int nt = 0; nt < 8; nt++)
                #pragma unroll
                for (int j = 0; j < 4; j++) s[nt][j] = 0.f;

            #pragma unroll
            for (int kc = 0; kc < 4; kc++) {
                uint32_t kfh[16], kfl[16];
                #pragma unroll
                for (int np = 0; np < 4; np++) {
                    uint32_t off = (uint32_t)(((np * 16 + ((lane >> 4) << 3) + (lane & 7)) * FSTR
                                     + kc * 16 + (((lane >> 3) & 1) << 3)) * 2);
                    LDMATRIX_X4(kfh[4 * np], kfh[4 * np + 1], kfh[4 * np + 2], kfh[4 * np + 3], sKh + off);
                    LDMATRIX_X4(kfl[4 * np], kfl[4 * np + 1], kfl[4 * np + 2], kfl[4 * np + 3], sKl + off);
                }
                #pragma unroll
                for (int nt = 0; nt < 8; nt++) MMA_BF16(s[nt], qfh[kc], &kfh[nt * 2]);
                #pragma unroll
                for (int nt = 0; nt < 8; nt++) MMA_BF16(s[nt], qfl[kc], &kfh[nt * 2]);
                #pragma unroll
                for (int nt = 0; nt < 8; nt++) MMA_BF16(s[nt], qfh[kc], &kfl[nt * 2]);
            }

            // ---- scale + causal mask ----
            const bool need_mask = (kb * 64 + 63) > warpR;
            #pragma unroll
            for (int nt = 0; nt < 8; nt++) {
                const int colg = kb * 64 + nt * 8 + ((lane & 3) << 1);
                const int r0g  = warpR + (lane >> 2);
                #pragma unroll
                for (int j = 0; j < 4; j++) {
                    float v = s[nt][j] * 0.125f;
                    if (need_mask) {
                        int colj = colg + (j & 1);
                        int rowj = r0g + ((j >> 1) << 3);
                        if (colj > rowj) v = -1e30f;
                    }
                    s[nt][j] = v;
                }
            }

            // ---- online softmax (rows r and r+8) ----
            float rm0 = -1e30f, rm1 = -1e30f;
            #pragma unroll
            for (int nt = 0; nt < 8; nt++) {
                rm0 = fmaxf(rm0, fmaxf(s[nt][0], s[nt][1]));
                rm1 = fmaxf(rm1, fmaxf(s[nt][2], s[nt][3]));
            }
            rm0 = fmaxf(rm0, __shfl_xor_sync(0xffffffffu, rm0, 1));
            rm0 = fmaxf(rm0, __shfl_xor_sync(0xffffffffu, rm0, 2));
            rm1 = fmaxf(rm1, __shfl_xor_sync(0xffffffffu, rm1, 1));
            rm1 = fmaxf(rm1, __shfl_xor_sync(0xffffffffu, rm1, 2));

            const float mn0 = fmaxf(m0, rm0), mn1 = fmaxf(m1, rm1);
            const float cr0 = __expf(m0 - mn0), cr1 = __expf(m1 - mn1);
            m0 = mn0; m1 = mn1;

            float rs0 = 0.f, rs1 = 0.f;
            #pragma unroll
            for (int nt = 0; nt < 8; nt++) {
                s[nt][0] = __expf(s[nt][0] - mn0);
                s[nt][1] = __expf(s[nt][1] - mn0);
                s[nt][2] = __expf(s[nt][2] - mn1);
                s[nt][3] = __expf(s[nt][3] - mn1);
                rs0 += s[nt][0] + s[nt][1];
                rs1 += s[nt][2] + s[nt][3];
            }
            rs0 += __shfl_xor_sync(0xffffffffu, rs0, 1);
            rs0 += __shfl_xor_sync(0xffffffffu, rs0, 2);
            rs1 += __shfl_xor_sync(0xffffffffu, rs1, 1);
            rs1 += __shfl_xor_sync(0xffffffffu, rs1, 2);
            l0 = l0 * cr0 + rs0;
            l1 = l1 * cr1 + rs1;

            #pragma unroll
            for (int nt = 0; nt < 8; nt++) {
                o[nt][0] *= cr0; o[nt][1] *= cr0;
                o[nt][2] *= cr1; o[nt][3] *= cr1;
            }

            // ---- pack P to hi/lo A-fragments (accum -> A-frag identity) ----
            uint32_t pfh[4][4], pfl[4][4];
            #pragma unroll
            for (int kc = 0; kc < 4; kc++) {
                #pragma unroll
                for (int q = 0; q < 4; q++) {
                    const int nt = 2 * kc + (q >> 1);
                    const int j0 = (q & 1) << 1;
                    float a = s[nt][j0], b2 = s[nt][j0 + 1];
                    float ah = __bfloat162float(__float2bfloat16(a));
                    float bh = __bfloat162float(__float2bfloat16(b2));
                    pfh[kc][q] = pack_bf16x2(ah, bh);
                    pfl[kc][q] = pack_bf16x2(a - ah, b2 - bh);
                }
            }

            // ---- O += Ph Vh + Pl Vh + Ph Vl ----
            #pragma unroll
            for (int kc = 0; kc < 4; kc++) {
                uint32_t vfh[16], vfl[16];
                #pragma unroll
                for (int np = 0; np < 4; np++) {
                    uint32_t off = (uint32_t)(((kc * 16 + (lane & 15)) * FSTR
                                     + np * 16 + ((lane >> 4) << 3)) * 2);
                    LDMATRIX_X4T(vfh[4 * np], vfh[4 * np + 1], vfh[4 * np + 2], vfh[4 * np + 3], sVh + off);
                    LDMATRIX_X4T(vfl[4 * np], vfl[4 * np + 1], vfl[4 * np + 2], vfl[4 * np + 3], sVl + off);
                }
                #pragma unroll
                for (int nt = 0; nt < 8; nt++) MMA_BF16(o[nt], pfh[kc], &vfh[nt * 2]);
                #pragma unroll
                for (int nt = 0; nt < 8; nt++) MMA_BF16(o[nt], pfl[kc], &vfh[nt * 2]);
                #pragma unroll
                for (int nt = 0; nt < 8; nt++) MMA_BF16(o[nt], pfh[kc], &vfl[nt * 2]);
            }
            __syncthreads();
        }

        // ---- epilogue ----
        const float inv0 = 1.f / l0, inv1 = 1.f / l1;
        const int r0g = warpR + (lane >> 2);
        #pragma unroll
        for (int nt = 0; nt < 8; nt++) {
            const int col = cb + nt * 8 + ((lane & 3) << 1);
            float2 o0 = { o[nt][0] * inv0, o[nt][1] * inv0 };
            float2 o1 = { o[nt][2] * inv1, o[nt][3] * inv1 };
            *reinterpret_cast<float2*>(&Og[(size_t)r0g * DM + col])       = o0;
            *reinterpret_cast<float2*>(&Og[(size_t)(r0g + 8) * DM + col]) = o1;
        }
        __syncthreads();   // protect smem before next half restages
    }
}

// ---------------------------------------------------------------------------
// Launch
// ---------------------------------------------------------------------------
extern "C" void kernel_launch(void* const* d_in, const int* in_sizes, int n_in,
                              void* d_out, int out_size)
{
    const float* x  = (const float*)d_in[0];
    const float* Wq = (const float*)d_in[1];
    const float* bq = (const float*)d_in[2];
    const float* Wk = (const float*)d_in[3];
    const float* bk = (const float*)d_in[4];
    const float* Wv = (const float*)d_in[5];
    const float* bv = (const float*)d_in[6];
    const float* Wo = (const float*)d_in[7];
    const float* bo = (const float*)d_in[8];
    float* out = (float*)d_out;

    float* O;
    cudaGetSymbolAddress((void**)&O, g_O);
    __nv_bfloat16 *Qhp, *Qlp, *Khp, *Klp, *Vhp, *Vlp;
    cudaGetSymbolAddress((void**)&Qhp, g_Qh); cudaGetSymbolAddress((void**)&Qlp, g_Ql);
    cudaGetSymbolAddress((void**)&Khp, g_Kh); cudaGetSymbolAddress((void**)&Klp, g_Kl);
    cudaGetSymbolAddress((void**)&Vhp, g_Vh); cudaGetSymbolAddress((void**)&Vlp, g_Vl);
    __nv_bfloat16 *xhi, *xlo, *Ohi, *Olo;
    cudaGetSymbolAddress((void**)&xhi, g_xhi);
    cudaGetSymbolAddress((void**)&xlo, g_xlo);
    cudaGetSymbolAddress((void**)&Ohi, g_Ohi);
    cudaGetSymbolAddress((void**)&Olo, g_Olo);
    __nv_bfloat16 *Wqh, *Wql, *Wkh, *Wkl, *Wvh, *Wvl, *Woh, *Wol;
    cudaGetSymbolAddress((void**)&Wqh, g_Wqh); cudaGetSymbolAddress((void**)&Wql, g_Wql);
    cudaGetSymbolAddress((void**)&Wkh, g_Wkh); cudaGetSymbolAddress((void**)&Wkl, g_Wkl);
    cudaGetSymbolAddress((void**)&Wvh, g_Wvh); cudaGetSymbolAddress((void**)&Wvl, g_Wvl);
    cudaGetSymbolAddress((void**)&Woh, g_Woh); cudaGetSymbolAddress((void**)&Wol, g_Wol);

    cudaFuncSetAttribute(flash_mma, cudaFuncAttributeMaxDynamicSharedMemorySize, F_SMEM_B);

    dim3 tg(DM / 32, DM / 32);
    dim3 gg(DM / 128, NTOK / 128);   // (8, 16)

    convert_split<<<NTOK * DM / 1024, 256>>>(x, xhi, xlo);
    transpose_split<<<tg, 256>>>(Wq, Wqh, Wql);
    transpose_split<<<tg, 256>>>(Wk, Wkh, Wkl);
    transpose_split<<<tg, 256>>>(Wv, Wvh, Wvl);
    transpose_split<<<tg, 256>>>(Wo, Woh, Wol);

    gemm_mma<true><<<gg, 256, G_SMEM>>>(xhi, xlo, Wqh, Wql, bq, nullptr, Qhp, Qlp);
    gemm_mma<true><<<gg, 256, G_SMEM>>>(xhi, xlo, Wkh, Wkl, bk, nullptr, Khp, Klp);
    gemm_mma<true><<<gg, 256, G_SMEM>>>(xhi, xlo, Wvh, Wvl, bv, nullptr, Vhp, Vlp);

    flash_mma<<<dim3(8, NH), 256, F_SMEM_B>>>(Qhp, Qlp, Khp, Klp, Vhp, Vlp, O);

    convert_split<<<NTOK * DM / 1024, 256>>>(O, Ohi, Olo);
    gemm_mma<false><<<gg, 256, G_SMEM>>>(Ohi, Olo, Woh, Wol, bo, out, nullptr, nullptr);
}

// round 10
// speedup vs baseline: 6.7571x; 2.1048x over previous
#include <cuda_runtime.h>
#include <cuda_fp16.h>
#include <cstdint>
#include <float.h>

#define NTOK 2048
#define DM   1024
#define NH   16
#define HD   64

// ---------------------------------------------------------------------------
// Scratch (__device__ globals; allocation-free rule)
// ---------------------------------------------------------------------------
__device__ __half g_xf[NTOK * DM];            // x in fp16
__device__ __half g_Qf[NTOK * DM];
__device__ __half g_Kf[NTOK * DM];
__device__ __half g_Vf[NTOK * DM];
__device__ __half g_Of[NTOK * DM];            // attention output in fp16
// transposed weights [N][K] fp16
__device__ __half g_Wqt[DM * DM], g_Wkt[DM * DM], g_Wvt[DM * DM], g_Wot[DM * DM];

// ---------------------------------------------------------------------------
// PTX helpers (base-target tensor path; tcgen05 unavailable at compute_103)
// ---------------------------------------------------------------------------
__device__ __forceinline__ uint32_t smem_u32(const void* p) {
    uint32_t a;
    asm("{ .reg .u64 t; cvta.to.shared.u64 t, %1; cvt.u32.u64 %0, t; }" : "=r"(a) : "l"(p));
    return a;
}

#define LDMATRIX_X4(r0, r1, r2, r3, addr) \
    asm volatile("ldmatrix.sync.aligned.m8n8.x4.shared.b16 {%0,%1,%2,%3}, [%4];" \
                 : "=r"(r0), "=r"(r1), "=r"(r2), "=r"(r3) : "r"(addr))
#define LDMATRIX_X4T(r0, r1, r2, r3, addr) \
    asm volatile("ldmatrix.sync.aligned.m8n8.x4.trans.shared.b16 {%0,%1,%2,%3}, [%4];" \
                 : "=r"(r0), "=r"(r1), "=r"(r2), "=r"(r3) : "r"(addr))
#define LDMATRIX_X2(r0, r1, addr) \
    asm volatile("ldmatrix.sync.aligned.m8n8.x2.shared.b16 {%0,%1}, [%2];" \
                 : "=r"(r0), "=r"(r1) : "r"(addr))
#define MMA_F16(d, a, b) \
    asm volatile("mma.sync.aligned.m16n8k16.row.col.f32.f16.f16.f32 " \
                 "{%0,%1,%2,%3}, {%4,%5,%6,%7}, {%8,%9}, {%0,%1,%2,%3};" \
                 : "+f"((d)[0]), "+f"((d)[1]), "+f"((d)[2]), "+f"((d)[3]) \
                 : "r"((a)[0]), "r"((a)[1]), "r"((a)[2]), "r"((a)[3]), \
                   "r"((b)[0]), "r"((b)[1]))

__device__ __forceinline__ uint32_t pack_h2(float a, float b) {
    __half2 t = __floats2half2_rn(a, b);
    return *reinterpret_cast<uint32_t*>(&t);
}

// ---------------------------------------------------------------------------
// fp32 -> fp16 elementwise
// ---------------------------------------------------------------------------
__global__ __launch_bounds__(256)
void convert_f16(const float* __restrict__ src, __half* __restrict__ dst)
{
    int i4 = blockIdx.x * 256 + threadIdx.x;
    float4 v = reinterpret_cast<const float4*>(src)[i4];
    uint2 o;
    o.x = pack_h2(v.x, v.y);
    o.y = pack_h2(v.z, v.w);
    reinterpret_cast<uint2*>(dst)[i4] = o;
}

// ---------------------------------------------------------------------------
// All 4 weights: W [K,N] fp32 -> Wt [N,K] fp16 (transpose), z selects matrix
// ---------------------------------------------------------------------------
__global__ __launch_bounds__(256)
void transpose4(const float* __restrict__ W0, const float* __restrict__ W1,
                const float* __restrict__ W2, const float* __restrict__ W3,
                __half* __restrict__ T0, __half* __restrict__ T1,
                __half* __restrict__ T2, __half* __restrict__ T3)
{
    const int z = blockIdx.z;
    const float* W = (z == 0) ? W0 : (z == 1) ? W1 : (z == 2) ? W2 : W3;
    __half* T      = (z == 0) ? T0 : (z == 1) ? T1 : (z == 2) ? T2 : T3;

    __shared__ float t[32][33];
    const int n0 = blockIdx.x * 32, k0 = blockIdx.y * 32;
    const int tx = threadIdx.x & 31, ty = threadIdx.x >> 5;   // 32 x 8
    #pragma unroll
    for (int i = 0; i < 4; i++)
        t[ty + 8 * i][tx] = W[(size_t)(k0 + ty + 8 * i) * DM + n0 + tx];
    __syncthreads();
    #pragma unroll
    for (int i = 0; i < 4; i++)
        T[(size_t)(n0 + ty + 8 * i) * DM + k0 + tx] = __float2half(t[tx][ty + 8 * i]);
}

// ---------------------------------------------------------------------------
// fp16 GEMM via mma.sync: C = A[M,K] @ Bt^T + bias.
// 128x128 CTA tile, BK=32, 256 threads = 8 warps (2 M x 4 N), double-buffered
// smem, one __syncthreads per chunk. blockIdx.z selects (B, bias, out).
// ---------------------------------------------------------------------------
#define GSTRIDE 40                       // halfs per smem row (32 data + 8 pad)
#define GMAT_B  (128 * GSTRIDE * 2)      // 10240 B per matrix
#define GBUF_B  (2 * GMAT_B)             // A + B per stage
// total static smem: 2 stages * 20480 = 40960 B

template<bool F32OUT>
__global__ __launch_bounds__(256)
void gemm_f16(const __half* __restrict__ A,
              const __half* __restrict__ B0, const __half* __restrict__ B1,
              const __half* __restrict__ B2,
              const float* __restrict__ bias0, const float* __restrict__ bias1,
              const float* __restrict__ bias2,
              __half* __restrict__ Ch0, __half* __restrict__ Ch1,
              __half* __restrict__ Ch2, float* __restrict__ Cf)
{
    __shared__ __align__(16) char sm[2 * GBUF_B];

    const int z = blockIdx.z;
    const __half* B    = (z == 0) ? B0 : (z == 1) ? B1 : B2;
    const float* bias  = (z == 0) ? bias0 : (z == 1) ? bias1 : bias2;
    __half* Ch         = (z == 0) ? Ch0 : (z == 1) ? Ch1 : Ch2;

    const int tid  = threadIdx.x;
    const int wid  = tid >> 5, lane = tid & 31;
    const int wm   = wid >> 2, wn = wid & 3;          // 2 x 4 warp grid
    const int col0 = blockIdx.x * 128;                // N
    const int row0 = blockIdx.y * 128;                // M

    const uint32_t sbase = smem_u32(sm);

    // staging map: chunk id c (0..511) -> r = c>>2, col8 = (c&3)*8
    const int st_r0 = (tid + 0)   >> 2, st_c0 = ((tid + 0)   & 3) << 3;
    const int st_r1 = (tid + 256) >> 2, st_c1 = ((tid + 256) & 3) << 3;

    const __half* Ap0 = A + (size_t)(row0 + st_r0) * DM + st_c0;
    const __half* Ap1 = A + (size_t)(row0 + st_r1) * DM + st_c1;
    const __half* Bp0 = B + (size_t)(col0 + st_r0) * DM + st_c0;
    const __half* Bp1 = B + (size_t)(col0 + st_r1) * DM + st_c1;

    uint4 pa0, pa1, pb0, pb1;
    pa0 = *reinterpret_cast<const uint4*>(Ap0);
    pa1 = *reinterpret_cast<const uint4*>(Ap1);
    pb0 = *reinterpret_cast<const uint4*>(Bp0);
    pb1 = *reinterpret_cast<const uint4*>(Bp1);

    const uint32_t d0 = (uint32_t)(st_r0 * GSTRIDE + st_c0) * 2;
    const uint32_t d1 = (uint32_t)(st_r1 * GSTRIDE + st_c1) * 2;

    // prologue store into buffer 0
    *reinterpret_cast<uint4*>(sm + 0 * GBUF_B + d0)          = pa0;
    *reinterpret_cast<uint4*>(sm + 0 * GBUF_B + d1)          = pa1;
    *reinterpret_cast<uint4*>(sm + 0 * GBUF_B + GMAT_B + d0) = pb0;
    *reinterpret_cast<uint4*>(sm + 0 * GBUF_B + GMAT_B + d1) = pb1;

    // fragment smem offsets
    const int aRow = wm * 64 + (lane & 15);
    const int aK8  = (lane >> 4) << 3;
    const int bl   = lane & 15;
    const int bRow = wn * 32 + (bl & 7);
    const int bK8  = (bl >> 3) << 3;

    float acc[4][4][4] = {};

    #pragma unroll 1
    for (int c = 0; c < DM / 32; c++) {
        __syncthreads();

        if (c + 1 < DM / 32) {
            const int k0n = (c + 1) * 32;
            pa0 = *reinterpret_cast<const uint4*>(Ap0 + k0n);
            pa1 = *reinterpret_cast<const uint4*>(Ap1 + k0n);
            pb0 = *reinterpret_cast<const uint4*>(Bp0 + k0n);
            pb1 = *reinterpret_cast<const uint4*>(Bp1 + k0n);
        }

        const uint32_t sA = sbase + (c & 1) * GBUF_B;
        const uint32_t sB = sA + GMAT_B;

        #pragma unroll
        for (int ks = 0; ks < 32; ks += 16) {
            uint32_t bf[4][2];
            #pragma unroll
            for (int nt = 0; nt < 4; nt++) {
                uint32_t off = (uint32_t)((bRow + nt * 8) * GSTRIDE + ks + bK8) * 2;
                LDMATRIX_X2(bf[nt][0], bf[nt][1], sB + off);
            }
            #pragma unroll
            for (int mt = 0; mt < 4; mt++) {
                uint32_t af[4];
                uint32_t off = (uint32_t)((aRow + mt * 16) * GSTRIDE + ks + aK8) * 2;
                LDMATRIX_X4(af[0], af[1], af[2], af[3], sA + off);
                #pragma unroll
                for (int nt = 0; nt < 4; nt++) MMA_F16(acc[mt][nt], af, bf[nt]);
            }
        }

        if (c + 1 < DM / 32) {
            char* dst = sm + ((c + 1) & 1) * GBUF_B;
            *reinterpret_cast<uint4*>(dst + d0)          = pa0;
            *reinterpret_cast<uint4*>(dst + d1)          = pa1;
            *reinterpret_cast<uint4*>(dst + GMAT_B + d0) = pb0;
            *reinterpret_cast<uint4*>(dst + GMAT_B + d1) = pb1;
        }
    }

    // epilogue
    const int qr = lane >> 2, qc = (lane & 3) << 1;
    #pragma unroll
    for (int nt = 0; nt < 4; nt++) {
        const int col = col0 + wn * 32 + nt * 8 + qc;
        const float2 bb = *reinterpret_cast<const float2*>(&bias[col]);
        #pragma unroll
        for (int mt = 0; mt < 4; mt++) {
            const int r = row0 + wm * 64 + mt * 16 + qr;
            float v00 = acc[mt][nt][0] + bb.x, v01 = acc[mt][nt][1] + bb.y;
            float v10 = acc[mt][nt][2] + bb.x, v11 = acc[mt][nt][3] + bb.y;
            if (F32OUT) {
                float2 o0 = { v00, v01 }, o1 = { v10, v11 };
                *reinterpret_cast<float2*>(&Cf[(size_t)r * DM + col])       = o0;
                *reinterpret_cast<float2*>(&Cf[(size_t)(r + 8) * DM + col]) = o1;
            } else {
                *reinterpret_cast<uint32_t*>(&Ch[(size_t)r * DM + col])       = pack_h2(v00, v01);
                *reinterpret_cast<uint32_t*>(&Ch[(size_t)(r + 8) * DM + col]) = pack_h2(v10, v11);
            }
        }
    }
}

// ---------------------------------------------------------------------------
// fp16 flash attention (causal) via mma.sync, fp32 softmax.
// CTA = 128 q-rows x 1 head; 8 warps x 16 rows; K-tile = 64.
// Double-buffered K/V smem, one __syncthreads per K-tile.
// Causal skip: fully-masked fragment tiles are skipped (uniform per-warp).
// Pairing: CTA handles q-tiles {p, 15-p} -> uniform 36 K-tiles per CTA.
// ---------------------------------------------------------------------------
#define FSTR 72   // smem row stride (halfs)
// dynamic smem (half elems): Q 128 rows; K/V double-buffered 64 rows each
#define F_Q        0
#define F_K(b)     ((128 + (b) * 128) * FSTR)
#define F_V(b)     ((192 + (b) * 128) * FSTR)
#define F_SMEM_B   (384 * FSTR * 2)   // 55296 B

__global__ __launch_bounds__(256, 1)
void flash_f16(const __half* __restrict__ Qg, const __half* __restrict__ Kg,
               const __half* __restrict__ Vg, __half* __restrict__ Og)
{
    extern __shared__ __half fsm[];

    const int pairi = blockIdx.x;     // 0..7
    const int h     = blockIdx.y;     // 0..15
    const int tid   = threadIdx.x;
    const int wid   = tid >> 5, lane = tid & 31;
    const int cb    = h * HD;

    const uint32_t sb = smem_u32(fsm);
    char* smc = reinterpret_cast<char*>(fsm);

    // K/V staging map: vid 0..511 -> r = vid>>3, c8 = (vid&7)*8; 2 per thread
    const int kv_r0 = (tid + 0)   >> 3, kv_c0 = ((tid + 0)   & 7) << 3;
    const int kv_r1 = (tid + 256) >> 3, kv_c1 = ((tid + 256) & 7) << 3;
    const size_t gkv0 = (size_t)kv_r0 * DM + cb + kv_c0;
    const size_t gkv1 = (size_t)kv_r1 * DM + cb + kv_c1;
    const uint32_t kvd0 = (uint32_t)(kv_r0 * FSTR + kv_c0) * 2;
    const uint32_t kvd1 = (uint32_t)(kv_r1 * FSTR + kv_c1) * 2;

    #pragma unroll 1
    for (int half_i = 0; half_i < 2; half_i++) {
        const int qb    = (half_i == 0) ? pairi : (15 - pairi);
        const int row0  = qb * 128;
        const int kbmax = 2 * qb + 1;   // inclusive
        const int warpR = row0 + wid * 16;

        // stage Q tile (128 x 64 halfs)
        #pragma unroll
        for (int s = 0; s < 4; s++) {
            int vid = tid + 256 * s;
            int r = vid >> 3, c8 = (vid & 7) << 3;
            uint4 v = *reinterpret_cast<const uint4*>(Qg + (size_t)(row0 + r) * DM + cb + c8);
            *reinterpret_cast<uint4*>(smc + (F_Q + r * FSTR + c8) * 2) = v;
        }

        // stage K/V tile 0 into buffer 0
        {
            uint4 k0 = *reinterpret_cast<const uint4*>(Kg + gkv0);
            uint4 k1 = *reinterpret_cast<const uint4*>(Kg + gkv1);
            uint4 v0 = *reinterpret_cast<const uint4*>(Vg + gkv0);
            uint4 v1 = *reinterpret_cast<const uint4*>(Vg + gkv1);
            *reinterpret_cast<uint4*>(smc + F_K(0) * 2 + kvd0) = k0;
            *reinterpret_cast<uint4*>(smc + F_K(0) * 2 + kvd1) = k1;
            *reinterpret_cast<uint4*>(smc + F_V(0) * 2 + kvd0) = v0;
            *reinterpret_cast<uint4*>(smc + F_V(0) * 2 + kvd1) = v1;
        }
        __syncthreads();

        // Q fragments (held in regs all half)
        uint32_t qf[4][4];
        {
            uint32_t off = sb + F_Q * 2
                + (uint32_t)(((wid * 16 + (lane & 15)) * FSTR + ((lane >> 4) << 3)) * 2);
            #pragma unroll
            for (int kc = 0; kc < 4; kc++)
                LDMATRIX_X4(qf[kc][0], qf[kc][1], qf[kc][2], qf[kc][3], off + kc * 32);
        }

        float m0 = -1e30f, m1 = -1e30f, l0 = 0.f, l1 = 0.f;
        float o[8][4] = {};

        uint4 pk0, pk1, pv0, pv1;

        #pragma unroll 1
        for (int kb = 0; kb <= kbmax; kb++) {
            // prefetch next K/V tile into regs (overlaps compute)
            if (kb < kbmax) {
                const size_t nb = (size_t)((kb + 1) * 64) * DM;
                pk0 = *reinterpret_cast<const uint4*>(Kg + nb + gkv0);
                pk1 = *reinterpret_cast<const uint4*>(Kg + nb + gkv1);
                pv0 = *reinterpret_cast<const uint4*>(Vg + nb + gkv0);
                pv1 = *reinterpret_cast<const uint4*>(Vg + nb + gkv1);
            }

            // fully-masked K-tile for this warp? (uniform branch)
            if (kb * 64 <= warpR + 15) {
                const uint32_t sK = sb + F_K(kb & 1) * 2;
                const uint32_t sV = sb + F_V(kb & 1) * 2;

                // ---- S = Q K^T (16 x 64 per warp), skip dead fragments ----
                float s[8][4];
                #pragma unroll
                for (int nt = 0; nt < 8; nt++) {
                    const bool live = (kb * 64 + nt * 8) <= (warpR + 15);
                    const float init = live ? 0.f : -1e30f;
                    s[nt][0] = init; s[nt][1] = init; s[nt][2] = init; s[nt][3] = init;
                }

                #pragma unroll
                for (int kc = 0; kc < 4; kc++) {
                    uint32_t kf[16];
                    #pragma unroll
                    for (int np = 0; np < 4; np++) {
                        if ((kb * 64 + np * 16) <= (warpR + 15)) {
                            uint32_t off = sK + (uint32_t)(((np * 16 + ((lane >> 4) << 3) + (lane & 7)) * FSTR
                                             + kc * 16 + (((lane >> 3) & 1) << 3)) * 2);
                            LDMATRIX_X4(kf[4 * np], kf[4 * np + 1], kf[4 * np + 2], kf[4 * np + 3], off);
                        }
                    }
                    #pragma unroll
                    for (int nt = 0; nt < 8; nt++)
                        if ((kb * 64 + nt * 8) <= (warpR + 15))
                            MMA_F16(s[nt], qf[kc], &kf[nt * 2]);
                }

                // ---- scale + causal mask (live fragments only) ----
                const bool need_mask = (kb * 64 + 63) > warpR;
                #pragma unroll
                for (int nt = 0; nt < 8; nt++) {
                    if ((kb * 64 + nt * 8) <= (warpR + 15)) {
                        const int colg = kb * 64 + nt * 8 + ((lane & 3) << 1);
                        const int r0g  = warpR + (lane >> 2);
                        #pragma unroll
                        for (int j = 0; j < 4; j++) {
                            float v = s[nt][j] * 0.125f;
                            if (need_mask) {
                                int colj = colg + (j & 1);
                                int rowj = r0g + ((j >> 1) << 3);
                                if (colj > rowj) v = -1e30f;
                            }
                            s[nt][j] = v;
                        }
                    }
                }

                // ---- online softmax (rows r and r+8) ----
                float rm0 = -1e30f, rm1 = -1e30f;
                #pragma unroll
                for (int nt = 0; nt < 8; nt++) {
                    rm0 = fmaxf(rm0, fmaxf(s[nt][0], s[nt][1]));
                    rm1 = fmaxf(rm1, fmaxf(s[nt][2], s[nt][3]));
                }
                rm0 = fmaxf(rm0, __shfl_xor_sync(0xffffffffu, rm0, 1));
                rm0 = fmaxf(rm0, __shfl_xor_sync(0xffffffffu, rm0, 2));
                rm1 = fmaxf(rm1, __shfl_xor_sync(0xffffffffu, rm1, 1));
                rm1 = fmaxf(rm1, __shfl_xor_sync(0xffffffffu, rm1, 2));

                const float mn0 = fmaxf(m0, rm0), mn1 = fmaxf(m1, rm1);
                const float cr0 = __expf(m0 - mn0), cr1 = __expf(m1 - mn1);
                m0 = mn0; m1 = mn1;

                float rs0 = 0.f, rs1 = 0.f;
                #pragma unroll
                for (int nt = 0; nt < 8; nt++) {
                    s[nt][0] = __expf(s[nt][0] - mn0);
                    s[nt][1] = __expf(s[nt][1] - mn0);
                    s[nt][2] = __expf(s[nt][2] - mn1);
                    s[nt][3] = __expf(s[nt][3] - mn1);
                    rs0 += s[nt][0] + s[nt][1];
                    rs1 += s[nt][2] + s[nt][3];
                }
                rs0 += __shfl_xor_sync(0xffffffffu, rs0, 1);
                rs0 += __shfl_xor_sync(0xffffffffu, rs0, 2);
                rs1 += __shfl_xor_sync(0xffffffffu, rs1, 1);
                rs1 += __shfl_xor_sync(0xffffffffu, rs1, 2);
                l0 = l0 * cr0 + rs0;
                l1 = l1 * cr1 + rs1;

                #pragma unroll
                for (int nt = 0; nt < 8; nt++) {
                    o[nt][0] *= cr0; o[nt][1] *= cr0;
                    o[nt][2] *= cr1; o[nt][3] *= cr1;
                }

                // ---- O += P V (skip dead kc groups) ----
                #pragma unroll
                for (int kc = 0; kc < 4; kc++) {
                    if ((kb * 64 + kc * 16) <= (warpR + 15)) {
                        uint32_t pf[4];
                        pf[0] = pack_h2(s[2 * kc][0],     s[2 * kc][1]);
                        pf[1] = pack_h2(s[2 * kc][2],     s[2 * kc][3]);
                        pf[2] = pack_h2(s[2 * kc + 1][0], s[2 * kc + 1][1]);
                        pf[3] = pack_h2(s[2 * kc + 1][2], s[2 * kc + 1][3]);

                        uint32_t vf[16];
                        #pragma unroll
                        for (int np = 0; np < 4; np++) {
                            uint32_t off = sV + (uint32_t)(((kc * 16 + (lane & 15)) * FSTR
                                             + np * 16 + ((lane >> 4) << 3)) * 2);
                            LDMATRIX_X4T(vf[4 * np], vf[4 * np + 1], vf[4 * np + 2], vf[4 * np + 3], off);
                        }
                        #pragma unroll
                        for (int nt = 0; nt < 8; nt++) MMA_F16(o[nt], pf, &vf[nt * 2]);
                    }
                }
            }

            // store prefetched tile into the other buffer
            if (kb < kbmax) {
                char* dk = smc + F_K((kb + 1) & 1) * 2;
                char* dv = smc + F_V((kb + 1) & 1) * 2;
                *reinterpret_cast<uint4*>(dk + kvd0) = pk0;
                *reinterpret_cast<uint4*>(dk + kvd1) = pk1;
                *reinterpret_cast<uint4*>(dv + kvd0) = pv0;
                *reinterpret_cast<uint4*>(dv + kvd1) = pv1;
            }
            __syncthreads();
        }

        // ---- epilogue: fp16 output ----
        const float inv0 = 1.f / l0, inv1 = 1.f / l1;
        const int r0g = warpR + (lane >> 2);
        #pragma unroll
        for (int nt = 0; nt < 8; nt++) {
            const int col = cb + nt * 8 + ((lane & 3) << 1);
            *reinterpret_cast<uint32_t*>(&Og[(size_t)r0g * DM + col]) =
                pack_h2(o[nt][0] * inv0, o[nt][1] * inv0);
            *reinterpret_cast<uint32_t*>(&Og[(size_t)(r0g + 8) * DM + col]) =
                pack_h2(o[nt][2] * inv1, o[nt][3] * inv1);
        }
        __syncthreads();   // protect smem before next half restages
    }
}

// ---------------------------------------------------------------------------
// Launch
// ---------------------------------------------------------------------------
extern "C" void kernel_launch(void* const* d_in, const int* in_sizes, int n_in,
                              void* d_out, int out_size)
{
    const float* x  = (const float*)d_in[0];
    const float* Wq = (const float*)d_in[1];
    const float* bq = (const float*)d_in[2];
    const float* Wk = (const float*)d_in[3];
    const float* bk = (const float*)d_in[4];
    const float* Wv = (const float*)d_in[5];
    const float* bv = (const float*)d_in[6];
    const float* Wo = (const float*)d_in[7];
    const float* bo = (const float*)d_in[8];
    float* out = (float*)d_out;

    __half *xf, *Qf, *Kf, *Vf, *Of, *Wqt, *Wkt, *Wvt, *Wot;
    cudaGetSymbolAddress((void**)&xf, g_xf);
    cudaGetSymbolAddress((void**)&Qf, g_Qf);
    cudaGetSymbolAddress((void**)&Kf, g_Kf);
    cudaGetSymbolAddress((void**)&Vf, g_Vf);
    cudaGetSymbolAddress((void**)&Of, g_Of);
    cudaGetSymbolAddress((void**)&Wqt, g_Wqt);
    cudaGetSymbolAddress((void**)&Wkt, g_Wkt);
    cudaGetSymbolAddress((void**)&Wvt, g_Wvt);
    cudaGetSymbolAddress((void**)&Wot, g_Wot);

    cudaFuncSetAttribute(flash_f16, cudaFuncAttributeMaxDynamicSharedMemorySize, F_SMEM_B);

    // x -> fp16
    convert_f16<<<NTOK * DM / 1024, 256>>>(x, xf);
    // all 4 weight transposes in one launch
    transpose4<<<dim3(DM / 32, DM / 32, 4), 256>>>(Wq, Wk, Wv, Wo, Wqt, Wkt, Wvt, Wot);

    // fused QKV projections (z selects weight/bias/output)
    gemm_f16<false><<<dim3(DM / 128, NTOK / 128, 3), 256>>>(
        xf, Wqt, Wkt, Wvt, bq, bk, bv, Qf, Kf, Vf, nullptr);

    // attention (fp16 in/out)
    flash_f16<<<dim3(8, NH), 256, F_SMEM_B>>>(Qf, Kf, Vf, Of);

    // output projection -> fp32 result
    gemm_f16<true><<<dim3(DM / 128, NTOK / 128, 1), 256>>>(
        Of, Wot, nullptr, nullptr, bo, nullptr, nullptr, nullptr, nullptr, nullptr, out);
}

// round 11
// speedup vs baseline: 7.4748x; 1.1062x over previous
#include <cuda_runtime.h>
#include <cuda_fp16.h>
#include <cstdint>
#include <float.h>

#define NTOK 2048
#define DM   1024
#define NH   16
#define HD   64

// ---------------------------------------------------------------------------
// Scratch (__device__ globals; allocation-free rule)
// ---------------------------------------------------------------------------
__device__ __half g_xf[NTOK * DM];            // x in fp16
__device__ __half g_Qf[NTOK * DM];
__device__ __half g_Kf[NTOK * DM];
__device__ __half g_Vf[NTOK * DM];
__device__ __half g_Of[NTOK * DM];            // attention output in fp16
// weights in fp16, ORIGINAL [K,N] layout (no transpose needed: B fragments
// are loaded with ldmatrix.trans from k-row-major smem)
__device__ __half g_Wqf[DM * DM], g_Wkf[DM * DM], g_Wvf[DM * DM], g_Wof[DM * DM];

// ---------------------------------------------------------------------------
// PTX helpers (base-target tensor path; tcgen05 unavailable at compute_103)
// ---------------------------------------------------------------------------
__device__ __forceinline__ uint32_t smem_u32(const void* p) {
    uint32_t a;
    asm("{ .reg .u64 t; cvta.to.shared.u64 t, %1; cvt.u32.u64 %0, t; }" : "=r"(a) : "l"(p));
    return a;
}

#define LDMATRIX_X4(r0, r1, r2, r3, addr) \
    asm volatile("ldmatrix.sync.aligned.m8n8.x4.shared.b16 {%0,%1,%2,%3}, [%4];" \
                 : "=r"(r0), "=r"(r1), "=r"(r2), "=r"(r3) : "r"(addr))
#define LDMATRIX_X4T(r0, r1, r2, r3, addr) \
    asm volatile("ldmatrix.sync.aligned.m8n8.x4.trans.shared.b16 {%0,%1,%2,%3}, [%4];" \
                 : "=r"(r0), "=r"(r1), "=r"(r2), "=r"(r3) : "r"(addr))
#define MMA_F16(d, a, b) \
    asm volatile("mma.sync.aligned.m16n8k16.row.col.f32.f16.f16.f32 " \
                 "{%0,%1,%2,%3}, {%4,%5,%6,%7}, {%8,%9}, {%0,%1,%2,%3};" \
                 : "+f"((d)[0]), "+f"((d)[1]), "+f"((d)[2]), "+f"((d)[3]) \
                 : "r"((a)[0]), "r"((a)[1]), "r"((a)[2]), "r"((a)[3]), \
                   "r"((b)[0]), "r"((b)[1]))

__device__ __forceinline__ uint32_t pack_h2(float a, float b) {
    __half2 t = __floats2half2_rn(a, b);
    return *reinterpret_cast<uint32_t*>(&t);
}

// ---------------------------------------------------------------------------
// fp32 -> fp16 elementwise (x)
// ---------------------------------------------------------------------------
__global__ __launch_bounds__(256)
void convert_f16(const float* __restrict__ src, __half* __restrict__ dst)
{
    int i4 = blockIdx.x * 256 + threadIdx.x;
    float4 v = reinterpret_cast<const float4*>(src)[i4];
    uint2 o;
    o.x = pack_h2(v.x, v.y);
    o.y = pack_h2(v.z, v.w);
    reinterpret_cast<uint2*>(dst)[i4] = o;
}

// ---------------------------------------------------------------------------
// All 4 weights fp32 -> fp16 elementwise, [K,N] layout kept. z selects matrix.
// ---------------------------------------------------------------------------
__global__ __launch_bounds__(256)
void convert_w4(const float* __restrict__ W0, const float* __restrict__ W1,
                const float* __restrict__ W2, const float* __restrict__ W3,
                __half* __restrict__ T0, __half* __restrict__ T1,
                __half* __restrict__ T2, __half* __restrict__ T3)
{
    const int z = blockIdx.z;
    const float* W = (z == 0) ? W0 : (z == 1) ? W1 : (z == 2) ? W2 : W3;
    __half* T      = (z == 0) ? T0 : (z == 1) ? T1 : (z == 2) ? T2 : T3;
    int i4 = blockIdx.x * 256 + threadIdx.x;
    float4 v = reinterpret_cast<const float4*>(W)[i4];
    uint2 o;
    o.x = pack_h2(v.x, v.y);
    o.y = pack_h2(v.z, v.w);
    reinterpret_cast<uint2*>(T)[i4] = o;
}

// ---------------------------------------------------------------------------
// fp16 GEMM via mma.sync: C = A[M,K] @ B + bias, B in [K,N] layout.
// B fragments via ldmatrix.x4.trans (same pattern as flash V path).
// 128x128 CTA tile, BK=32, 256 threads = 8 warps (2 M x 4 N), double-buffered.
// blockIdx.z selects (B, bias, out).
// ---------------------------------------------------------------------------
#define ASTRIDE 40                        // halfs per A smem row (32 + 8 pad)
#define ABYTES  (128 * ASTRIDE * 2)       // 10240
#define BSTRIDE 136                       // halfs per B smem row (128 + 8 pad)
#define BBYTES  (32 * BSTRIDE * 2)        // 8704
#define STAGEB  (ABYTES + BBYTES)         // 18944; x2 stages = 37888 (static ok)

template<bool F32OUT>
__global__ __launch_bounds__(256)
void gemm_f16(const __half* __restrict__ A,
              const __half* __restrict__ B0, const __half* __restrict__ B1,
              const __half* __restrict__ B2,
              const float* __restrict__ bias0, const float* __restrict__ bias1,
              const float* __restrict__ bias2,
              __half* __restrict__ Ch0, __half* __restrict__ Ch1,
              __half* __restrict__ Ch2, float* __restrict__ Cf)
{
    __shared__ __align__(16) char sm[2 * STAGEB];

    const int z = blockIdx.z;
    const __half* B    = (z == 0) ? B0 : (z == 1) ? B1 : B2;
    const float* bias  = (z == 0) ? bias0 : (z == 1) ? bias1 : bias2;
    __half* Ch         = (z == 0) ? Ch0 : (z == 1) ? Ch1 : Ch2;

    const int tid  = threadIdx.x;
    const int wid  = tid >> 5, lane = tid & 31;
    const int wm   = wid >> 2, wn = wid & 3;          // 2 x 4 warp grid
    const int col0 = blockIdx.x * 128;                // N
    const int row0 = blockIdx.y * 128;                // M

    const uint32_t sbase = smem_u32(sm);

    // A staging: 128 rows x 32 k halfs = 512 uint4; tid -> r=tid>>2, k8=(tid&3)*8
    const int at_r0 = (tid + 0)   >> 2, at_c0 = ((tid + 0)   & 3) << 3;
    const int at_r1 = (tid + 256) >> 2, at_c1 = ((tid + 256) & 3) << 3;
    const __half* Ap0 = A + (size_t)(row0 + at_r0) * DM + at_c0;
    const __half* Ap1 = A + (size_t)(row0 + at_r1) * DM + at_c1;
    const uint32_t ad0 = (uint32_t)(at_r0 * ASTRIDE + at_c0) * 2;
    const uint32_t ad1 = (uint32_t)(at_r1 * ASTRIDE + at_c1) * 2;

    // B staging: 32 k-rows x 128 n halfs = 512 uint4; tid -> kr=tid>>4, n8=(tid&15)*8
    const int bt_r0 = tid >> 4;              // 0..15
    const int bt_c0 = (tid & 15) << 3;       // 0..120
    const __half* Bp0 = B + (size_t)bt_r0 * DM + col0 + bt_c0;
    const __half* Bp1 = B + (size_t)(bt_r0 + 16) * DM + col0 + bt_c0;
    const uint32_t bd0 = (uint32_t)(bt_r0 * BSTRIDE + bt_c0) * 2;
    const uint32_t bd1 = (uint32_t)((bt_r0 + 16) * BSTRIDE + bt_c0) * 2;
    const size_t chunkB = (size_t)32 * DM;

    uint4 pa0, pa1, pb0, pb1;
    pa0 = *reinterpret_cast<const uint4*>(Ap0);
    pa1 = *reinterpret_cast<const uint4*>(Ap1);
    pb0 = *reinterpret_cast<const uint4*>(Bp0);
    pb1 = *reinterpret_cast<const uint4*>(Bp1);

    // prologue store into buffer 0
    *reinterpret_cast<uint4*>(sm + ad0)          = pa0;
    *reinterpret_cast<uint4*>(sm + ad1)          = pa1;
    *reinterpret_cast<uint4*>(sm + ABYTES + bd0) = pb0;
    *reinterpret_cast<uint4*>(sm + ABYTES + bd1) = pb1;

    // fragment offsets
    const int aRow = wm * 64 + (lane & 15);
    const int aK8  = (lane >> 4) << 3;
    // B frag (trans): row = ks + (lane&15), col = wn*32 + g*16 + (lane>>4)*8
    const int bRowL = lane & 15;
    const int bC8   = (lane >> 4) << 3;

    float acc[4][4][4] = {};

    #pragma unroll 1
    for (int c = 0; c < DM / 32; c++) {
        __syncthreads();

        if (c + 1 < DM / 32) {
            const int k0n = (c + 1) * 32;
            pa0 = *reinterpret_cast<const uint4*>(Ap0 + k0n);
            pa1 = *reinterpret_cast<const uint4*>(Ap1 + k0n);
            pb0 = *reinterpret_cast<const uint4*>(Bp0 + (size_t)(c + 1) * chunkB);
            pb1 = *reinterpret_cast<const uint4*>(Bp1 + (size_t)(c + 1) * chunkB);
        }

        const uint32_t sA = sbase + (c & 1) * STAGEB;
        const uint32_t sB = sA + ABYTES;

        #pragma unroll
        for (int ks = 0; ks < 32; ks += 16) {
            uint32_t bf[8];
            #pragma unroll
            for (int g = 0; g < 2; g++) {
                uint32_t off = sB + (uint32_t)(((ks + bRowL) * BSTRIDE
                                 + wn * 32 + g * 16 + bC8) * 2);
                LDMATRIX_X4T(bf[4 * g], bf[4 * g + 1], bf[4 * g + 2], bf[4 * g + 3], off);
            }
            #pragma unroll
            for (int mt = 0; mt < 4; mt++) {
                uint32_t af[4];
                uint32_t off = sA + (uint32_t)(((aRow + mt * 16) * ASTRIDE + ks + aK8) * 2);
                LDMATRIX_X4(af[0], af[1], af[2], af[3], off);
                #pragma unroll
                for (int nt = 0; nt < 4; nt++) MMA_F16(acc[mt][nt], af, &bf[nt * 2]);
            }
        }

        if (c + 1 < DM / 32) {
            char* dst = sm + ((c + 1) & 1) * STAGEB;
            *reinterpret_cast<uint4*>(dst + ad0)          = pa0;
            *reinterpret_cast<uint4*>(dst + ad1)          = pa1;
            *reinterpret_cast<uint4*>(dst + ABYTES + bd0) = pb0;
            *reinterpret_cast<uint4*>(dst + ABYTES + bd1) = pb1;
        }
    }

    // epilogue
    const int qr = lane >> 2, qc = (lane & 3) << 1;
    #pragma unroll
    for (int nt = 0; nt < 4; nt++) {
        const int col = col0 + wn * 32 + nt * 8 + qc;
        const float2 bb = *reinterpret_cast<const float2*>(&bias[col]);
        #pragma unroll
        for (int mt = 0; mt < 4; mt++) {
            const int r = row0 + wm * 64 + mt * 16 + qr;
            float v00 = acc[mt][nt][0] + bb.x, v01 = acc[mt][nt][1] + bb.y;
            float v10 = acc[mt][nt][2] + bb.x, v11 = acc[mt][nt][3] + bb.y;
            if (F32OUT) {
                float2 o0 = { v00, v01 }, o1 = { v10, v11 };
                *reinterpret_cast<float2*>(&Cf[(size_t)r * DM + col])       = o0;
                *reinterpret_cast<float2*>(&Cf[(size_t)(r + 8) * DM + col]) = o1;
            } else {
                *reinterpret_cast<uint32_t*>(&Ch[(size_t)r * DM + col])       = pack_h2(v00, v01);
                *reinterpret_cast<uint32_t*>(&Ch[(size_t)(r + 8) * DM + col]) = pack_h2(v10, v11);
            }
        }
    }
}

// ---------------------------------------------------------------------------
// fp16 flash attention (causal) via mma.sync, fp32 softmax.
// CTA = 64 q-rows x 1 head, 128 threads (4 warps x 16 rows); K-tile = 64.
// 2 CTAs/SM (regs ~200 x 128 thr, 46 KB smem) -> softmax of one CTA overlaps
// MMAs of the other. Big-tiles-first: qb = 31 - blockIdx.y.
// Double-buffered K/V smem; diagonal fragment skip (warp w: nt <= 2w+1).
// ---------------------------------------------------------------------------
#define FSTR 72   // smem row stride (halfs)
// smem rows (halfs): Q 64 | K0 64 | V0 64 | K1 64 | V1 64  = 320 rows
#define F_Q        0
#define F_K(b)     ((64  + (b) * 128) * FSTR)
#define F_V(b)     ((128 + (b) * 128) * FSTR)
#define F_SMEM_B   (320 * FSTR * 2)   // 46080 B (< 48K default dyn smem)

__global__ __launch_bounds__(128, 2)
void flash_f16(const __half* __restrict__ Qg, const __half* __restrict__ Kg,
               const __half* __restrict__ Vg, __half* __restrict__ Og)
{
    extern __shared__ __half fsm[];

    const int h     = blockIdx.x;          // 0..15
    const int qb    = 31 - blockIdx.y;     // big tiles first
    const int tid   = threadIdx.x;
    const int wid   = tid >> 5, lane = tid & 31;
    const int cb    = h * HD;
    const int row0  = qb * 64;
    const int kbmax = qb;                  // inclusive
    const int warpR = row0 + wid * 16;

    const uint32_t sb = smem_u32(fsm);
    char* smc = reinterpret_cast<char*>(fsm);

    // 64x64 tile staging map: vid = tid + 128*s -> r = vid>>3, c8 = (vid&7)*8
    size_t   gkv[4];
    uint32_t kvd[4];
    #pragma unroll
    for (int s = 0; s < 4; s++) {
        int vid = tid + 128 * s;
        int r = vid >> 3, c8 = (vid & 7) << 3;
        gkv[s] = (size_t)r * DM + cb + c8;
        kvd[s] = (uint32_t)(r * FSTR + c8) * 2;
    }

    // stage Q tile (64 x 64 halfs)
    #pragma unroll
    for (int s = 0; s < 4; s++) {
        uint4 v = *reinterpret_cast<const uint4*>(Qg + (size_t)row0 * DM + gkv[s]);
        *reinterpret_cast<uint4*>(smc + F_Q * 2 + kvd[s]) = v;
    }

    // stage K/V tile 0 into buffer 0
    uint4 pk[4], pv[4];
    #pragma unroll
    for (int s = 0; s < 4; s++) {
        pk[s] = *reinterpret_cast<const uint4*>(Kg + gkv[s]);
        pv[s] = *reinterpret_cast<const uint4*>(Vg + gkv[s]);
    }
    #pragma unroll
    for (int s = 0; s < 4; s++) {
        *reinterpret_cast<uint4*>(smc + F_K(0) * 2 + kvd[s]) = pk[s];
        *reinterpret_cast<uint4*>(smc + F_V(0) * 2 + kvd[s]) = pv[s];
    }
    __syncthreads();

    // Q fragments (held in regs)
    uint32_t qf[4][4];
    {
        uint32_t off = sb + F_Q * 2
            + (uint32_t)(((wid * 16 + (lane & 15)) * FSTR + ((lane >> 4) << 3)) * 2);
        #pragma unroll
        for (int kc = 0; kc < 4; kc++)
            LDMATRIX_X4(qf[kc][0], qf[kc][1], qf[kc][2], qf[kc][3], off + kc * 32);
    }

    float m0 = -1e30f, m1 = -1e30f, l0 = 0.f, l1 = 0.f;
    float o[8][4] = {};

    #pragma unroll 1
    for (int kb = 0; kb <= kbmax; kb++) {
        // prefetch next K/V tile into regs (overlaps compute)
        if (kb < kbmax) {
            const size_t nb = (size_t)((kb + 1) * 64) * DM;
            #pragma unroll
            for (int s = 0; s < 4; s++) {
                pk[s] = *reinterpret_cast<const uint4*>(Kg + nb + gkv[s]);
                pv[s] = *reinterpret_cast<const uint4*>(Vg + nb + gkv[s]);
            }
        }

        const uint32_t sK = sb + F_K(kb & 1) * 2;
        const uint32_t sV = sb + F_V(kb & 1) * 2;

        // ---- S = Q K^T (16 x 64 per warp), skip dead fragments ----
        float s[8][4];
        #pragma unroll
        for (int nt = 0; nt < 8; nt++) {
            const bool live = (kb * 64 + nt * 8) <= (warpR + 15);
            const float init = live ? 0.f : -1e30f;
            s[nt][0] = init; s[nt][1] = init; s[nt][2] = init; s[nt][3] = init;
        }

        #pragma unroll
        for (int kc = 0; kc < 4; kc++) {
            uint32_t kf[16];
            #pragma unroll
            for (int np = 0; np < 4; np++) {
                if ((kb * 64 + np * 16) <= (warpR + 15)) {
                    uint32_t off = sK + (uint32_t)(((np * 16 + ((lane >> 4) << 3) + (lane & 7)) * FSTR
                                     + kc * 16 + (((lane >> 3) & 1) << 3)) * 2);
                    LDMATRIX_X4(kf[4 * np], kf[4 * np + 1], kf[4 * np + 2], kf[4 * np + 3], off);
                }
            }
            #pragma unroll
            for (int nt = 0; nt < 8; nt++)
                if ((kb * 64 + nt * 8) <= (warpR + 15))
                    MMA_F16(s[nt], qf[kc], &kf[nt * 2]);
        }

        // ---- scale + causal mask (live fragments only) ----
        const bool need_mask = (kb * 64 + 63) > warpR;
        #pragma unroll
        for (int nt = 0; nt < 8; nt++) {
            if ((kb * 64 + nt * 8) <= (warpR + 15)) {
                const int colg = kb * 64 + nt * 8 + ((lane & 3) << 1);
                const int r0g  = warpR + (lane >> 2);
                #pragma unroll
                for (int j = 0; j < 4; j++) {
                    float v = s[nt][j] * 0.125f;
                    if (need_mask) {
                        int colj = colg + (j & 1);
                        int rowj = r0g + ((j >> 1) << 3);
                        if (colj > rowj) v = -1e30f;
                    }
                    s[nt][j] = v;
                }
            }
        }

        // ---- online softmax (rows r and r+8) ----
        float rm0 = -1e30f, rm1 = -1e30f;
        #pragma unroll
        for (int nt = 0; nt < 8; nt++) {
            rm0 = fmaxf(rm0, fmaxf(s[nt][0], s[nt][1]));
            rm1 = fmaxf(rm1, fmaxf(s[nt][2], s[nt][3]));
        }
        rm0 = fmaxf(rm0, __shfl_xor_sync(0xffffffffu, rm0, 1));
        rm0 = fmaxf(rm0, __shfl_xor_sync(0xffffffffu, rm0, 2));
        rm1 = fmaxf(rm1, __shfl_xor_sync(0xffffffffu, rm1, 1));
        rm1 = fmaxf(rm1, __shfl_xor_sync(0xffffffffu, rm1, 2));

        const float mn0 = fmaxf(m0, rm0), mn1 = fmaxf(m1, rm1);
        const float cr0 = __expf(m0 - mn0), cr1 = __expf(m1 - mn1);
        m0 = mn0; m1 = mn1;

        float rs0 = 0.f, rs1 = 0.f;
        #pragma unroll
        for (int nt = 0; nt < 8; nt++) {
            s[nt][0] = __expf(s[nt][0] - mn0);
            s[nt][1] = __expf(s[nt][1] - mn0);
            s[nt][2] = __expf(s[nt][2] - mn1);
            s[nt][3] = __expf(s[nt][3] - mn1);
            rs0 += s[nt][0] + s[nt][1];
            rs1 += s[nt][2] + s[nt][3];
        }
        rs0 += __shfl_xor_sync(0xffffffffu, rs0, 1);
        rs0 += __shfl_xor_sync(0xffffffffu, rs0, 2);
        rs1 += __shfl_xor_sync(0xffffffffu, rs1, 1);
        rs1 += __shfl_xor_sync(0xffffffffu, rs1, 2);
        l0 = l0 * cr0 + rs0;
        l1 = l1 * cr1 + rs1;

        #pragma unroll
        for (int nt = 0; nt < 8; nt++) {
            o[nt][0] *= cr0; o[nt][1] *= cr0;
            o[nt][2] *= cr1; o[nt][3] *= cr1;
        }

        // ---- O += P V (skip dead kc groups) ----
        #pragma unroll
        for (int kc = 0; kc < 4; kc++) {
            if ((kb * 64 + kc * 16) <= (warpR + 15)) {
                uint32_t pf[4];
                pf[0] = pack_h2(s[2 * kc][0],     s[2 * kc][1]);
                pf[1] = pack_h2(s[2 * kc][2],     s[2 * kc][3]);
                pf[2] = pack_h2(s[2 * kc + 1][0], s[2 * kc + 1][1]);
                pf[3] = pack_h2(s[2 * kc + 1][2], s[2 * kc + 1][3]);

                uint32_t vf[16];
                #pragma unroll
                for (int np = 0; np < 4; np++) {
                    uint32_t off = sV + (uint32_t)(((kc * 16 + (lane & 15)) * FSTR
                                     + np * 16 + ((lane >> 4) << 3)) * 2);
                    LDMATRIX_X4T(vf[4 * np], vf[4 * np + 1], vf[4 * np + 2], vf[4 * np + 3], off);
                }
                #pragma unroll
                for (int nt = 0; nt < 8; nt++) MMA_F16(o[nt], pf, &vf[nt * 2]);
            }
        }

        // store prefetched tile into the other buffer
        if (kb < kbmax) {
            char* dk = smc + F_K((kb + 1) & 1) * 2;
            char* dv = smc + F_V((kb + 1) & 1) * 2;
            #pragma unroll
            for (int s2 = 0; s2 < 4; s2++) {
                *reinterpret_cast<uint4*>(dk + kvd[s2]) = pk[s2];
                *reinterpret_cast<uint4*>(dv + kvd[s2]) = pv[s2];
            }
        }
        __syncthreads();
    }

    // ---- epilogue: fp16 output ----
    const float inv0 = 1.f / l0, inv1 = 1.f / l1;
    const int r0g = warpR + (lane >> 2);
    #pragma unroll
    for (int nt = 0; nt < 8; nt++) {
        const int col = cb + nt * 8 + ((lane & 3) << 1);
        *reinterpret_cast<uint32_t*>(&Og[(size_t)r0g * DM + col]) =
            pack_h2(o[nt][0] * inv0, o[nt][1] * inv0);
        *reinterpret_cast<uint32_t*>(&Og[(size_t)(r0g + 8) * DM + col]) =
            pack_h2(o[nt][2] * inv1, o[nt][3] * inv1);
    }
}

// ---------------------------------------------------------------------------
// Launch
// ---------------------------------------------------------------------------
extern "C" void kernel_launch(void* const* d_in, const int* in_sizes, int n_in,
                              void* d_out, int out_size)
{
    const float* x  = (const float*)d_in[0];
    const float* Wq = (const float*)d_in[1];
    const float* bq = (const float*)d_in[2];
    const float* Wk = (const float*)d_in[3];
    const float* bk = (const float*)d_in[4];
    const float* Wv = (const float*)d_in[5];
    const float* bv = (const float*)d_in[6];
    const float* Wo = (const float*)d_in[7];
    const float* bo = (const float*)d_in[8];
    float* out = (float*)d_out;

    __half *xf, *Qf, *Kf, *Vf, *Of, *Wqf, *Wkf, *Wvf, *Wof;
    cudaGetSymbolAddress((void**)&xf, g_xf);
    cudaGetSymbolAddress((void**)&Qf, g_Qf);
    cudaGetSymbolAddress((void**)&Kf, g_Kf);
    cudaGetSymbolAddress((void**)&Vf, g_Vf);
    cudaGetSymbolAddress((void**)&Of, g_Of);
    cudaGetSymbolAddress((void**)&Wqf, g_Wqf);
    cudaGetSymbolAddress((void**)&Wkf, g_Wkf);
    cudaGetSymbolAddress((void**)&Wvf, g_Wvf);
    cudaGetSymbolAddress((void**)&Wof, g_Wof);

    // x -> fp16; all 4 weights -> fp16 (no transpose)
    convert_f16<<<NTOK * DM / 1024, 256>>>(x, xf);
    convert_w4<<<dim3(DM * DM / 1024, 1, 4), 256>>>(Wq, Wk, Wv, Wo, Wqf, Wkf, Wvf, Wof);

    // fused QKV projections (z selects weight/bias/output)
    gemm_f16<false><<<dim3(DM / 128, NTOK / 128, 3), 256>>>(
        xf, Wqf, Wkf, Wvf, bq, bk, bv, Qf, Kf, Vf, nullptr);

    // attention (fp16 in/out), 64-row q-tiles, big-first, 2 CTAs/SM
    flash_f16<<<dim3(NH, 32), 128, F_SMEM_B>>>(Qf, Kf, Vf, Of);

    // output projection -> fp32 result
    gemm_f16<true><<<dim3(DM / 128, NTOK / 128, 1), 256>>>(
        Of, Wof, nullptr, nullptr, bo, nullptr, nullptr, nullptr, nullptr, nullptr, out);
}

// round 14
// speedup vs baseline: 9.2452x; 1.2368x over previous
#include <cuda_runtime.h>
#include <cuda_fp16.h>
#include <cstdint>
#include <float.h>

#define NTOK 2048
#define DM   1024
#define NH   16
#define HD   64

// ---------------------------------------------------------------------------
// Scratch (__device__ globals; allocation-free rule)
// ---------------------------------------------------------------------------
__device__ __half g_xf[NTOK * DM];            // x in fp16
__device__ __half g_Qf[NTOK * DM];            // pre-scaled by 0.125*log2e
__device__ __half g_Kf[NTOK * DM];
__device__ __half g_Vf[NTOK * DM];
__device__ __half g_Of[NTOK * DM];            // attention output in fp16
// weights in fp16, ORIGINAL [K,N] layout
__device__ __half g_Wqf[DM * DM], g_Wkf[DM * DM], g_Wvf[DM * DM], g_Wof[DM * DM];

// ---------------------------------------------------------------------------
// PTX helpers (base-target tensor path; tcgen05 unavailable at compute_103)
// ---------------------------------------------------------------------------
__device__ __forceinline__ uint32_t smem_u32(const void* p) {
    uint32_t a;
    asm("{ .reg .u64 t; cvta.to.shared.u64 t, %1; cvt.u32.u64 %0, t; }" : "=r"(a) : "l"(p));
    return a;
}

__device__ __forceinline__ float ex2f(float x) {   // MUFU.EX2 (2^x)
    float r;
    asm("ex2.approx.ftz.f32 %0, %1;" : "=f"(r) : "f"(x));
    return r;
}

#define LDMATRIX_X4(r0, r1, r2, r3, addr) \
    asm volatile("ldmatrix.sync.aligned.m8n8.x4.shared.b16 {%0,%1,%2,%3}, [%4];" \
                 : "=r"(r0), "=r"(r1), "=r"(r2), "=r"(r3) : "r"(addr))
#define LDMATRIX_X4T(r0, r1, r2, r3, addr) \
    asm volatile("ldmatrix.sync.aligned.m8n8.x4.trans.shared.b16 {%0,%1,%2,%3}, [%4];" \
                 : "=r"(r0), "=r"(r1), "=r"(r2), "=r"(r3) : "r"(addr))
#define MMA_F16(d, a, b) \
    asm volatile("mma.sync.aligned.m16n8k16.row.col.f32.f16.f16.f32 " \
                 "{%0,%1,%2,%3}, {%4,%5,%6,%7}, {%8,%9}, {%0,%1,%2,%3};" \
                 : "+f"((d)[0]), "+f"((d)[1]), "+f"((d)[2]), "+f"((d)[3]) \
                 : "r"((a)[0]), "r"((a)[1]), "r"((a)[2]), "r"((a)[3]), \
                   "r"((b)[0]), "r"((b)[1]))

__device__ __forceinline__ uint32_t pack_h2(float a, float b) {
    __half2 t = __floats2half2_rn(a, b);
    return *reinterpret_cast<uint32_t*>(&t);
}

// 0.125 * log2(e): folded into Q so softmax runs in exp2 domain
#define QSCALE 0.18033688011112042f

// ---------------------------------------------------------------------------
// Fused fp32 -> fp16 conversion: z=0 -> x (2M elems), z=1..4 -> weights (1M).
// Guard: weight slices use only the first DM*DM/1024 blocks.
// ---------------------------------------------------------------------------
__global__ __launch_bounds__(256)
void convert_all(const float* __restrict__ x,
                 const float* __restrict__ W0, const float* __restrict__ W1,
                 const float* __restrict__ W2, const float* __restrict__ W3,
                 __half* __restrict__ xf,
                 __half* __restrict__ T0, __half* __restrict__ T1,
                 __half* __restrict__ T2, __half* __restrict__ T3)
{
    const int z = blockIdx.z;
    if (z > 0 && blockIdx.x >= DM * DM / 1024) return;   // weights: 1M elems only
    const float* S = (z == 0) ? x : (z == 1) ? W0 : (z == 2) ? W1 : (z == 3) ? W2 : W3;
    __half* D      = (z == 0) ? xf : (z == 1) ? T0 : (z == 2) ? T1 : (z == 3) ? T2 : T3;
    int i4 = blockIdx.x * 256 + threadIdx.x;
    float4 v = reinterpret_cast<const float4*>(S)[i4];
    uint2 o;
    o.x = pack_h2(v.x, v.y);
    o.y = pack_h2(v.z, v.w);
    reinterpret_cast<uint2*>(D)[i4] = o;
}

// ---------------------------------------------------------------------------
// fp16 GEMM via mma.sync: C = A[M,K] @ B + bias, B in [K,N] layout.
// B fragments via ldmatrix.x4.trans. 128x128 CTA tile, BK=32, 256 threads,
// double-buffered. z selects (B, bias, out). z==0 (Q) output scaled by QSCALE.
// ---------------------------------------------------------------------------
#define ASTRIDE 40
#define ABYTES  (128 * ASTRIDE * 2)       // 10240
#define BSTRIDE 136
#define BBYTES  (32 * BSTRIDE * 2)        // 8704
#define STAGEB  (ABYTES + BBYTES)         // 18944

template<bool F32OUT>
__global__ __launch_bounds__(256)
void gemm_f16(const __half* __restrict__ A,
              const __half* __restrict__ B0, const __half* __restrict__ B1,
              const __half* __restrict__ B2,
              const float* __restrict__ bias0, const float* __restrict__ bias1,
              const float* __restrict__ bias2,
              __half* __restrict__ Ch0, __half* __restrict__ Ch1,
              __half* __restrict__ Ch2, float* __restrict__ Cf)
{
    __shared__ __align__(16) char sm[2 * STAGEB];

    const int z = blockIdx.z;
    const __half* B    = (z == 0) ? B0 : (z == 1) ? B1 : B2;
    const float* bias  = (z == 0) ? bias0 : (z == 1) ? bias1 : bias2;
    __half* Ch         = (z == 0) ? Ch0 : (z == 1) ? Ch1 : Ch2;
    const float osc    = (!F32OUT && z == 0) ? QSCALE : 1.0f;

    const int tid  = threadIdx.x;
    const int wid  = tid >> 5, lane = tid & 31;
    const int wm   = wid >> 2, wn = wid & 3;
    const int col0 = blockIdx.x * 128;
    const int row0 = blockIdx.y * 128;

    const uint32_t sbase = smem_u32(sm);

    const int at_r0 = (tid + 0)   >> 2, at_c0 = ((tid + 0)   & 3) << 3;
    const int at_r1 = (tid + 256) >> 2, at_c1 = ((tid + 256) & 3) << 3;
    const __half* Ap0 = A + (size_t)(row0 + at_r0) * DM + at_c0;
    const __half* Ap1 = A + (size_t)(row0 + at_r1) * DM + at_c1;
    const uint32_t ad0 = (uint32_t)(at_r0 * ASTRIDE + at_c0) * 2;
    const uint32_t ad1 = (uint32_t)(at_r1 * ASTRIDE + at_c1) * 2;

    const int bt_r0 = tid >> 4;
    const int bt_c0 = (tid & 15) << 3;
    const __half* Bp0 = B + (size_t)bt_r0 * DM + col0 + bt_c0;
    const __half* Bp1 = B + (size_t)(bt_r0 + 16) * DM + col0 + bt_c0;
    const uint32_t bd0 = (uint32_t)(bt_r0 * BSTRIDE + bt_c0) * 2;
    const uint32_t bd1 = (uint32_t)((bt_r0 + 16) * BSTRIDE + bt_c0) * 2;
    const size_t chunkB = (size_t)32 * DM;

    uint4 pa0, pa1, pb0, pb1;
    pa0 = *reinterpret_cast<const uint4*>(Ap0);
    pa1 = *reinterpret_cast<const uint4*>(Ap1);
    pb0 = *reinterpret_cast<const uint4*>(Bp0);
    pb1 = *reinterpret_cast<const uint4*>(Bp1);

    *reinterpret_cast<uint4*>(sm + ad0)          = pa0;
    *reinterpret_cast<uint4*>(sm + ad1)          = pa1;
    *reinterpret_cast<uint4*>(sm + ABYTES + bd0) = pb0;
    *reinterpret_cast<uint4*>(sm + ABYTES + bd1) = pb1;

    const int aRow = wm * 64 + (lane & 15);
    const int aK8  = (lane >> 4) << 3;
    const int bRowL = lane & 15;
    const int bC8   = (lane >> 4) << 3;

    float acc[4][4][4] = {};

    #pragma unroll 1
    for (int c = 0; c < DM / 32; c++) {
        __syncthreads();

        if (c + 1 < DM / 32) {
            const int k0n = (c + 1) * 32;
            pa0 = *reinterpret_cast<const uint4*>(Ap0 + k0n);
            pa1 = *reinterpret_cast<const uint4*>(Ap1 + k0n);
            pb0 = *reinterpret_cast<const uint4*>(Bp0 + (size_t)(c + 1) * chunkB);
            pb1 = *reinterpret_cast<const uint4*>(Bp1 + (size_t)(c + 1) * chunkB);
        }

        const uint32_t sA = sbase + (c & 1) * STAGEB;
        const uint32_t sB = sA + ABYTES;

        #pragma unroll
        for (int ks = 0; ks < 32; ks += 16) {
            uint32_t bf[8];
            #pragma unroll
            for (int g = 0; g < 2; g++) {
                uint32_t off = sB + (uint32_t)(((ks + bRowL) * BSTRIDE
                                 + wn * 32 + g * 16 + bC8) * 2);
                LDMATRIX_X4T(bf[4 * g], bf[4 * g + 1], bf[4 * g + 2], bf[4 * g + 3], off);
            }
            #pragma unroll
            for (int mt = 0; mt < 4; mt++) {
                uint32_t af[4];
                uint32_t off = sA + (uint32_t)(((aRow + mt * 16) * ASTRIDE + ks + aK8) * 2);
                LDMATRIX_X4(af[0], af[1], af[2], af[3], off);
                #pragma unroll
                for (int nt = 0; nt < 4; nt++) MMA_F16(acc[mt][nt], af, &bf[nt * 2]);
            }
        }

        if (c + 1 < DM / 32) {
            char* dst = sm + ((c + 1) & 1) * STAGEB;
            *reinterpret_cast<uint4*>(dst + ad0)          = pa0;
            *reinterpret_cast<uint4*>(dst + ad1)          = pa1;
            *reinterpret_cast<uint4*>(dst + ABYTES + bd0) = pb0;
            *reinterpret_cast<uint4*>(dst + ABYTES + bd1) = pb1;
        }
    }

    const int qr = lane >> 2, qc = (lane & 3) << 1;
    #pragma unroll
    for (int nt = 0; nt < 4; nt++) {
        const int col = col0 + wn * 32 + nt * 8 + qc;
        const float2 bb = *reinterpret_cast<const float2*>(&bias[col]);
        #pragma unroll
        for (int mt = 0; mt < 4; mt++) {
            const int r = row0 + wm * 64 + mt * 16 + qr;
            float v00 = (acc[mt][nt][0] + bb.x) * osc, v01 = (acc[mt][nt][1] + bb.y) * osc;
            float v10 = (acc[mt][nt][2] + bb.x) * osc, v11 = (acc[mt][nt][3] + bb.y) * osc;
            if (F32OUT) {
                float2 o0 = { v00, v01 }, o1 = { v10, v11 };
                *reinterpret_cast<float2*>(&Cf[(size_t)r * DM + col])       = o0;
                *reinterpret_cast<float2*>(&Cf[(size_t)(r + 8) * DM + col]) = o1;
            } else {
                *reinterpret_cast<uint32_t*>(&Ch[(size_t)r * DM + col])       = pack_h2(v00, v01);
                *reinterpret_cast<uint32_t*>(&Ch[(size_t)(r + 8) * DM + col]) = pack_h2(v10, v11);
            }
        }
    }
}

// ---------------------------------------------------------------------------
// fp16 flash attention (causal), exp2-domain softmax (Q pre-scaled).
// CTA = 64 q-rows x 1 head, 128 threads (4 warps x 16 rows); K-tile = 64.
// Dense/diagonal split: tiles kb < qb have NO masks or predicates.
// ---------------------------------------------------------------------------
#define FSTR 72   // smem row stride (halfs)
#define F_Q        0
#define F_K(b)     ((64  + (b) * 128) * FSTR)
#define F_V(b)     ((128 + (b) * 128) * FSTR)
#define F_SMEM_B   (320 * FSTR * 2)   // 46080 B

template<bool DIAG>
__device__ __forceinline__ void fa_tile(
    const int kb, const int warpR, const int lane,
    const uint32_t (&qf)[4][4], const uint32_t sK, const uint32_t sV,
    float (&o)[8][4], float& m0, float& m1, float& l0, float& l1)
{
    // ---- S = Q K^T (16 x 64 per warp) ----
    float s[8][4];
    #pragma unroll
    for (int nt = 0; nt < 8; nt++) {
        float init = 0.f;
        if (DIAG) init = ((kb * 64 + nt * 8) <= (warpR + 15)) ? 0.f : -1e30f;
        s[nt][0] = init; s[nt][1] = init; s[nt][2] = init; s[nt][3] = init;
    }

    #pragma unroll
    for (int kc = 0; kc < 4; kc++) {
        uint32_t kf[16];
        #pragma unroll
        for (int np = 0; np < 4; np++) {
            if (!DIAG || (kb * 64 + np * 16) <= (warpR + 15)) {
                uint32_t off = sK + (uint32_t)(((np * 16 + ((lane >> 4) << 3) + (lane & 7)) * FSTR
                                 + kc * 16 + (((lane >> 3) & 1) << 3)) * 2);
                LDMATRIX_X4(kf[4 * np], kf[4 * np + 1], kf[4 * np + 2], kf[4 * np + 3], off);
            }
        }
        #pragma unroll
        for (int nt = 0; nt < 8; nt++)
            if (!DIAG || (kb * 64 + nt * 8) <= (warpR + 15))
                MMA_F16(s[nt], qf[kc], &kf[nt * 2]);
    }

    // ---- causal mask (diagonal tile only) ----
    if (DIAG) {
        #pragma unroll
        for (int nt = 0; nt < 8; nt++) {
            if ((kb * 64 + nt * 8) <= (warpR + 15)) {
                const int colg = kb * 64 + nt * 8 + ((lane & 3) << 1);
                const int r0g  = warpR + (lane >> 2);
                #pragma unroll
                for (int j = 0; j < 4; j++) {
                    int colj = colg + (j & 1);
                    int rowj = r0g + ((j >> 1) << 3);
                    if (colj > rowj) s[nt][j] = -1e30f;
                }
            }
        }
    }

    // ---- online softmax, log2 domain ----
    float rm0 = -1e30f, rm1 = -1e30f;
    #pragma unroll
    for (int nt = 0; nt < 8; nt++) {
        rm0 = fmaxf(rm0, fmaxf(s[nt][0], s[nt][1]));
        rm1 = fmaxf(rm1, fmaxf(s[nt][2], s[nt][3]));
    }
    rm0 = fmaxf(rm0, __shfl_xor_sync(0xffffffffu, rm0, 1));
    rm0 = fmaxf(rm0, __shfl_xor_sync(0xffffffffu, rm0, 2));
    rm1 = fmaxf(rm1, __shfl_xor_sync(0xffffffffu, rm1, 1));
    rm1 = fmaxf(rm1, __shfl_xor_sync(0xffffffffu, rm1, 2));

    const float mn0 = fmaxf(m0, rm0), mn1 = fmaxf(m1, rm1);
    const float cr0 = ex2f(m0 - mn0), cr1 = ex2f(m1 - mn1);
    m0 = mn0; m1 = mn1;

    float rs0 = 0.f, rs1 = 0.f;
    #pragma unroll
    for (int nt = 0; nt < 8; nt++) {
        s[nt][0] = ex2f(s[nt][0] - mn0);
        s[nt][1] = ex2f(s[nt][1] - mn0);
        s[nt][2] = ex2f(s[nt][2] - mn1);
        s[nt][3] = ex2f(s[nt][3] - mn1);
        rs0 += s[nt][0] + s[nt][1];
        rs1 += s[nt][2] + s[nt][3];
    }
    rs0 += __shfl_xor_sync(0xffffffffu, rs0, 1);
    rs0 += __shfl_xor_sync(0xffffffffu, rs0, 2);
    rs1 += __shfl_xor_sync(0xffffffffu, rs1, 1);
    rs1 += __shfl_xor_sync(0xffffffffu, rs1, 2);
    l0 = l0 * cr0 + rs0;
    l1 = l1 * cr1 + rs1;

    #pragma unroll
    for (int nt = 0; nt < 8; nt++) {
        o[nt][0] *= cr0; o[nt][1] *= cr0;
        o[nt][2] *= cr1; o[nt][3] *= cr1;
    }

    // ---- O += P V ----
    #pragma unroll
    for (int kc = 0; kc < 4; kc++) {
        if (!DIAG || (kb * 64 + kc * 16) <= (warpR + 15)) {
            uint32_t pf[4];
            pf[0] = pack_h2(s[2 * kc][0],     s[2 * kc][1]);
            pf[1] = pack_h2(s[2 * kc][2],     s[2 * kc][3]);
            pf[2] = pack_h2(s[2 * kc + 1][0], s[2 * kc + 1][1]);
            pf[3] = pack_h2(s[2 * kc + 1][2], s[2 * kc + 1][3]);

            uint32_t vf[16];
            #pragma unroll
            for (int np = 0; np < 4; np++) {
                uint32_t off = sV + (uint32_t)(((kc * 16 + (lane & 15)) * FSTR
                                 + np * 16 + ((lane >> 4) << 3)) * 2);
                LDMATRIX_X4T(vf[4 * np], vf[4 * np + 1], vf[4 * np + 2], vf[4 * np + 3], off);
            }
            #pragma unroll
            for (int nt = 0; nt < 8; nt++) MMA_F16(o[nt], pf, &vf[nt * 2]);
        }
    }
}

__global__ __launch_bounds__(128, 2)
void flash_f16(const __half* __restrict__ Qg, const __half* __restrict__ Kg,
               const __half* __restrict__ Vg, __half* __restrict__ Og)
{
    extern __shared__ __half fsm[];

    const int h     = blockIdx.x;
    const int qb    = 31 - blockIdx.y;     // big tiles first
    const int tid   = threadIdx.x;
    const int wid   = tid >> 5, lane = tid & 31;
    const int cb    = h * HD;
    const int row0  = qb * 64;
    const int kbmax = qb;                  // diagonal tile index
    const int warpR = row0 + wid * 16;

    const uint32_t sb = smem_u32(fsm);
    char* smc = reinterpret_cast<char*>(fsm);

    size_t   gkv[4];
    uint32_t kvd[4];
    #pragma unroll
    for (int s = 0; s < 4; s++) {
        int vid = tid + 128 * s;
        int r = vid >> 3, c8 = (vid & 7) << 3;
        gkv[s] = (size_t)r * DM + cb + c8;
        kvd[s] = (uint32_t)(r * FSTR + c8) * 2;
    }

    // stage Q tile
    #pragma unroll
    for (int s = 0; s < 4; s++) {
        uint4 v = *reinterpret_cast<const uint4*>(Qg + (size_t)row0 * DM + gkv[s]);
        *reinterpret_cast<uint4*>(smc + F_Q * 2 + kvd[s]) = v;
    }

    // stage K/V tile 0 into buffer 0
    uint4 pk[4], pv[4];
    #pragma unroll
    for (int s = 0; s < 4; s++) {
        pk[s] = *reinterpret_cast<const uint4*>(Kg + gkv[s]);
        pv[s] = *reinterpret_cast<const uint4*>(Vg + gkv[s]);
    }
    #pragma unroll
    for (int s = 0; s < 4; s++) {
        *reinterpret_cast<uint4*>(smc + F_K(0) * 2 + kvd[s]) = pk[s];
        *reinterpret_cast<uint4*>(smc + F_V(0) * 2 + kvd[s]) = pv[s];
    }
    __syncthreads();

    // Q fragments
    uint32_t qf[4][4];
    {
        uint32_t off = sb + F_Q * 2
            + (uint32_t)(((wid * 16 + (lane & 15)) * FSTR + ((lane >> 4) << 3)) * 2);
        #pragma unroll
        for (int kc = 0; kc < 4; kc++)
            LDMATRIX_X4(qf[kc][0], qf[kc][1], qf[kc][2], qf[kc][3], off + kc * 32);
    }

    float m0 = -1e30f, m1 = -1e30f, l0 = 0.f, l1 = 0.f;
    float o[8][4] = {};

    // dense tiles: no masks, no predicates
    #pragma unroll 1
    for (int kb = 0; kb < kbmax; kb++) {
        const size_t nb = (size_t)((kb + 1) * 64) * DM;
        #pragma unroll
        for (int s = 0; s < 4; s++) {
            pk[s] = *reinterpret_cast<const uint4*>(Kg + nb + gkv[s]);
            pv[s] = *reinterpret_cast<const uint4*>(Vg + nb + gkv[s]);
        }

        fa_tile<false>(kb, warpR, lane, qf,
                       sb + F_K(kb & 1) * 2, sb + F_V(kb & 1) * 2,
                       o, m0, m1, l0, l1);

        char* dk = smc + F_K((kb + 1) & 1) * 2;
        char* dv = smc + F_V((kb + 1) & 1) * 2;
        #pragma unroll
        for (int s2 = 0; s2 < 4; s2++) {
            *reinterpret_cast<uint4*>(dk + kvd[s2]) = pk[s2];
            *reinterpret_cast<uint4*>(dv + kvd[s2]) = pv[s2];
        }
        __syncthreads();
    }

    // diagonal tile
    fa_tile<true>(kbmax, warpR, lane, qf,
                  sb + F_K(kbmax & 1) * 2, sb + F_V(kbmax & 1) * 2,
                  o, m0, m1, l0, l1);

    // ---- epilogue: fp16 output ----
    const float inv0 = 1.f / l0, inv1 = 1.f / l1;
    const int r0g = warpR + (lane >> 2);
    #pragma unroll
    for (int nt = 0; nt < 8; nt++) {
        const int col = cb + nt * 8 + ((lane & 3) << 1);
        *reinterpret_cast<uint32_t*>(&Og[(size_t)r0g * DM + col]) =
            pack_h2(o[nt][0] * inv0, o[nt][1] * inv0);
        *reinterpret_cast<uint32_t*>(&Og[(size_t)(r0g + 8) * DM + col]) =
            pack_h2(o[nt][2] * inv1, o[nt][3] * inv1);
    }
}

// ---------------------------------------------------------------------------
// Launch
// ---------------------------------------------------------------------------
extern "C" void kernel_launch(void* const* d_in, const int* in_sizes, int n_in,
                              void* d_out, int out_size)
{
    const float* x  = (const float*)d_in[0];
    const float* Wq = (const float*)d_in[1];
    const float* bq = (const float*)d_in[2];
    const float* Wk = (const float*)d_in[3];
    const float* bk = (const float*)d_in[4];
    const float* Wv = (const float*)d_in[5];
    const float* bv = (const float*)d_in[6];
    const float* Wo = (const float*)d_in[7];
    const float* bo = (const float*)d_in[8];
    float* out = (float*)d_out;

    __half *xf, *Qf, *Kf, *Vf, *Of, *Wqf, *Wkf, *Wvf, *Wof;
    cudaGetSymbolAddress((void**)&xf, g_xf);
    cudaGetSymbolAddress((void**)&Qf, g_Qf);
    cudaGetSymbolAddress((void**)&Kf, g_Kf);
    cudaGetSymbolAddress((void**)&Vf, g_Vf);
    cudaGetSymbolAddress((void**)&Of, g_Of);
    cudaGetSymbolAddress((void**)&Wqf, g_Wqf);
    cudaGetSymbolAddress((void**)&Wkf, g_Wkf);
    cudaGetSymbolAddress((void**)&Wvf, g_Wvf);
    cudaGetSymbolAddress((void**)&Wof, g_Wof);

    // fused conversions: x (2M elems) + all 4 weights (1M each, guarded)
    convert_all<<<dim3(NTOK * DM / 1024, 1, 5), 256>>>(
        x, Wq, Wk, Wv, Wo, xf, Wqf, Wkf, Wvf, Wof);

    // fused QKV projections (z=0 output pre-scaled for exp2 softmax)
    gemm_f16<false><<<dim3(DM / 128, NTOK / 128, 3), 256>>>(
        xf, Wqf, Wkf, Wvf, bq, bk, bv, Qf, Kf, Vf, nullptr);

    // attention
    flash_f16<<<dim3(NH, 32), 128, F_SMEM_B>>>(Qf, Kf, Vf, Of);

    // output projection -> fp32 result
    gemm_f16<true><<<dim3(DM / 128, NTOK / 128, 1), 256>>>(
        Of, Wof, nullptr, nullptr, bo, nullptr, nullptr, nullptr, nullptr, nullptr, out);
}